// round 7
// baseline (speedup 1.0000x reference)
#include <cuda_runtime.h>
#include <cuda_bf16.h>
#include <math.h>
#include <stdint.h>

// Problem constants
#define BB 8
#define LL 1024
#define DD 256
#define FF 11
#define TEMP_INV (1.0f/16.0f)
#define LN_EPS 1e-6f

// GEMM config: 128x128 CTA tile, K-slab 64, 16 warps (4m x 4n), warp tile 32x32,
// 3-stage cp.async pipeline, operands pre-split bf16 hi/lo in global.
#define SLAB 64
#define TB 16384                 // one 128x64 bf16 tile (128 rows x 128B)
#define STAGE_B (4*TB)           // AH AL BH BL = 64KB
#define STAGES 3
#define SMEM_DYN (STAGES*STAGE_B)   // 196608
#define NT 512

// ---------------------------------------------------------------------------
// Global scratch: bf16 pool + fp32 leftovers
// ---------------------------------------------------------------------------
#define E2M (BB*LL*DD)                    // 2,097,152
#define E8M ((size_t)BB*LL*LL)            // 8,388,608
#define EW  (DD*DD)                       // 65,536

#define O_QH   ((size_t)0*E2M)
#define O_QL   ((size_t)1*E2M)
#define O_KH   ((size_t)2*E2M)
#define O_KL   ((size_t)3*E2M)
#define O_VH   ((size_t)4*E2M)
#define O_VL   ((size_t)5*E2M)
#define O_QPH  ((size_t)6*E2M)
#define O_QPL  ((size_t)7*E2M)
#define O_KPH  ((size_t)8*E2M)
#define O_KPL  ((size_t)9*E2M)
#define O_Q2TH ((size_t)10*E2M)
#define O_Q2TL ((size_t)11*E2M)
#define O_K2TH ((size_t)12*E2M)
#define O_K2TL ((size_t)13*E2M)
#define O_VPTH ((size_t)14*E2M)
#define O_VPTL ((size_t)15*E2M)
#define O_Q2FH ((size_t)16*E2M)
#define O_Q2FL ((size_t)17*E2M)
#define O_K2FH ((size_t)18*E2M)
#define O_K2FL ((size_t)19*E2M)
#define O_OVH  ((size_t)20*E2M)
#define O_OVL  ((size_t)21*E2M)
#define O_WH   ((size_t)22*E2M)
#define O_WL   (O_WH + 6*EW)
#define O_FAH  (O_WL + 6*EW)
#define O_FAL  (O_FAH + E8M)
#define O_ATH  (O_FAL + E8M)
#define O_ATL  (O_ATH + E8M)
#define POOL_ELEMS (O_ATL + E8M)

__device__ __nv_bfloat16 g_pool[POOL_ELEMS];
__device__ float g_fc[E2M];
__device__ float g_attn_scratch[E8M];

// ---------------------------------------------------------------------------
// Helpers
// ---------------------------------------------------------------------------
__device__ __forceinline__ uint32_t smem_u32(const void* p) {
    uint32_t a;
    asm("{ .reg .u64 t; cvta.to.shared.u64 t, %1; cvt.u32.u64 %0, t; }"
        : "=r"(a) : "l"(p));
    return a;
}
__device__ __forceinline__ void cp16(uint32_t dst, const void* src) {
    asm volatile("cp.async.cg.shared.global [%0], [%1], 16;" :: "r"(dst), "l"(src));
}
#define CP_COMMIT() asm volatile("cp.async.commit_group;" ::: "memory")

__device__ __forceinline__ void ldsm_x4(uint32_t* r, uint32_t a) {
    asm volatile("ldmatrix.sync.aligned.m8n8.x4.shared.b16 {%0,%1,%2,%3}, [%4];"
        : "=r"(r[0]), "=r"(r[1]), "=r"(r[2]), "=r"(r[3]) : "r"(a));
}
__device__ __forceinline__ void mma16816(float* c, const uint32_t* a, const uint32_t* b) {
    asm volatile("mma.sync.aligned.m16n8k16.row.col.f32.bf16.bf16.f32 "
        "{%0,%1,%2,%3}, {%4,%5,%6,%7}, {%8,%9}, {%0,%1,%2,%3};"
        : "+f"(c[0]), "+f"(c[1]), "+f"(c[2]), "+f"(c[3])
        : "r"(a[0]), "r"(a[1]), "r"(a[2]), "r"(a[3]), "r"(b[0]), "r"(b[1]));
}
__device__ __forceinline__ void split2(float x, float y,
                                       __nv_bfloat162& h, __nv_bfloat162& l) {
    h = __floats2bfloat162_rn(x, y);
    l = __floats2bfloat162_rn(x - __bfloat162float(h.x), y - __bfloat162float(h.y));
}

// ---------------------------------------------------------------------------
// bf16x3 mma.sync GEMM body, operands pre-split bf16 hi/lo in global.
// NT pairs: C[m,n] = sum_k A[m,k]*B[n,k] over (set1,k1) then (set2,k2).
// MODE: 0 = bf16 hi/lo out; 1 = fp32 + residual; 2 = tanh/mask -> fp32 + hi/lo
// ---------------------------------------------------------------------------
template<int MODE>
__device__ __forceinline__
void tc_body(const __nv_bfloat16* __restrict__ A1h, const __nv_bfloat16* __restrict__ A1l,
             const __nv_bfloat16* __restrict__ B1h, const __nv_bfloat16* __restrict__ B1l,
             int k1, int lda1, int ldb1,
             const __nv_bfloat16* __restrict__ A2h, const __nv_bfloat16* __restrict__ A2l,
             const __nv_bfloat16* __restrict__ B2h, const __nv_bfloat16* __restrict__ B2l,
             int k2, int lda2, int ldb2,
             float* __restrict__ Cf, const float* __restrict__ add,
             __nv_bfloat16* __restrict__ Ch, __nv_bfloat16* __restrict__ Cl,
             int ldc, int len, int m0, int n0)
{
    extern __shared__ char smem[];
    const uint32_t sb = smem_u32(smem);
    const int tid = threadIdx.x;
    const int lane = tid & 31, wid = tid >> 5;
    const int wm = wid & 3, wn = wid >> 2;

    // cp.async thread mapping: t4 selects tile (AH,AL,BH,BL), row = 0..127
    const int t4 = tid >> 7, row = tid & 127;
    const uint32_t px = ((uint32_t)row & 7) << 4;
    const uint32_t drow = (uint32_t)t4 * TB + ((uint32_t)row << 7);

    const int n1 = k1 / SLAB;
    const int nslabs = n1 + (A2h ? k2 / SLAB : 0);

    auto issue = [&](int s) {
        const __nv_bfloat16 *ah, *al, *bh, *bl; int lda, ldb, k0;
        if (s < n1) { ah = A1h; al = A1l; bh = B1h; bl = B1l; lda = lda1; ldb = ldb1; k0 = s * SLAB; }
        else        { ah = A2h; al = A2l; bh = B2h; bl = B2l; lda = lda2; ldb = ldb2; k0 = (s - n1) * SLAB; }
        const __nv_bfloat16* base = (t4 == 0) ? ah : (t4 == 1) ? al : (t4 == 2) ? bh : bl;
        const int ld = (t4 < 2) ? lda : ldb;
        const int rr = ((t4 < 2) ? m0 : n0) + row;
        const char* src = (const char*)(base + (size_t)rr * ld + k0);
        const uint32_t dst = sb + (uint32_t)(s % STAGES) * STAGE_B + drow;
        #pragma unroll
        for (int c = 0; c < 8; c++)
            cp16(dst + (((uint32_t)c << 4) ^ px), src + (c << 4));
        CP_COMMIT();
    };

    issue(0);
    issue(1);

    float acc[2][4][4] = {};

    // ldmatrix lane addressing (128B rows, SW128-style XOR)
    const int a_row = wm * 32 + (lane & 15);
    const uint32_t a_colp = (lane >> 4) << 4;
    const uint32_t a_xor = (uint32_t)(a_row & 7) << 4;
    const int b_row = wn * 32 + ((lane >> 4) << 3) + (lane & 7);
    const uint32_t b_colp = ((lane >> 3) & 1) << 4;
    const uint32_t b_xor = (uint32_t)(b_row & 7) << 4;

    for (int s = 0; s < nslabs; s++) {
        if (s + 1 < nslabs) asm volatile("cp.async.wait_group 1;" ::: "memory");
        else                asm volatile("cp.async.wait_group 0;" ::: "memory");
        __syncthreads();
        // safe: buffer (s+2)%3 == (s-1)%3, whose compute all warps finished
        // before passing the sync above.
        if (s + 2 < nslabs) issue(s + 2);

        const uint32_t bo = sb + (uint32_t)(s % STAGES) * STAGE_B;
        #pragma unroll
        for (int kk = 0; kk < 4; kk++) {
            const uint32_t kb = kk << 5;
            uint32_t bH[8], bL[8];
            {
                uint32_t r = (uint32_t)b_row << 7;
                uint32_t c = (kb + b_colp) ^ b_xor;
                ldsm_x4(bH + 0, bo + 2*TB + r + c);
                ldsm_x4(bH + 4, bo + 2*TB + r + 2048 + c);
                ldsm_x4(bL + 0, bo + 3*TB + r + c);
                ldsm_x4(bL + 4, bo + 3*TB + r + 2048 + c);
            }
            #pragma unroll
            for (int mt = 0; mt < 2; mt++) {
                uint32_t aH[4], aL[4];
                uint32_t r = (uint32_t)(a_row + mt*16) << 7;
                uint32_t c = (kb + a_colp) ^ a_xor;
                ldsm_x4(aH, bo + r + c);
                ldsm_x4(aL, bo + TB + r + c);
                #pragma unroll
                for (int nt = 0; nt < 4; nt++) {
                    mma16816(acc[mt][nt], aH, bH + nt*2);
                    mma16816(acc[mt][nt], aH, bL + nt*2);
                    mma16816(acc[mt][nt], aL, bH + nt*2);
                }
            }
        }
    }

    // epilogue
    const int mg = m0 + wm * 32, ng = n0 + wn * 32;
    const int rq = lane >> 2, cq = (lane & 3) << 1;
    #pragma unroll
    for (int mt = 0; mt < 2; mt++) {
        #pragma unroll
        for (int nt = 0; nt < 4; nt++) {
            const float* a4 = acc[mt][nt];
            const int r0 = mg + mt*16 + rq, r1 = r0 + 8;
            const int c0 = ng + nt*8 + cq;
            if (MODE == 0) {
                __nv_bfloat162 h, l;
                split2(a4[0], a4[1], h, l);
                *(__nv_bfloat162*)(Ch + (size_t)r0*ldc + c0) = h;
                *(__nv_bfloat162*)(Cl + (size_t)r0*ldc + c0) = l;
                split2(a4[2], a4[3], h, l);
                *(__nv_bfloat162*)(Ch + (size_t)r1*ldc + c0) = h;
                *(__nv_bfloat162*)(Cl + (size_t)r1*ldc + c0) = l;
            } else if (MODE == 1) {
                float2 x0 = *(const float2*)(add + (size_t)r0*ldc + c0);
                float2 x1 = *(const float2*)(add + (size_t)r1*ldc + c0);
                *(float2*)(Cf + (size_t)r0*ldc + c0) = make_float2(a4[0]+x0.x, a4[1]+x0.y);
                *(float2*)(Cf + (size_t)r1*ldc + c0) = make_float2(a4[2]+x1.x, a4[3]+x1.y);
            } else {
                float t0 = (c0   < len) ? tanhf(a4[0]*TEMP_INV) : 0.f;
                float t1 = (c0+1 < len) ? tanhf(a4[1]*TEMP_INV) : 0.f;
                float t2 = (c0   < len) ? tanhf(a4[2]*TEMP_INV) : 0.f;
                float t3 = (c0+1 < len) ? tanhf(a4[3]*TEMP_INV) : 0.f;
                *(float2*)(Cf + (size_t)r0*ldc + c0) = make_float2(t0, t1);
                *(float2*)(Cf + (size_t)r1*ldc + c0) = make_float2(t2, t3);
                __nv_bfloat162 h, l;
                split2(t0, t1, h, l);
                *(__nv_bfloat162*)(Ch + (size_t)r0*ldc + c0) = h;
                *(__nv_bfloat162*)(Cl + (size_t)r0*ldc + c0) = l;
                split2(t2, t3, h, l);
                *(__nv_bfloat162*)(Ch + (size_t)r1*ldc + c0) = h;
                *(__nv_bfloat162*)(Cl + (size_t)r1*ldc + c0) = l;
            }
        }
    }
}

// ---------------------------------------------------------------------------
// Stage kernels
// ---------------------------------------------------------------------------
#define NO2 (const __nv_bfloat16*)nullptr, (const __nv_bfloat16*)nullptr, \
            (const __nv_bfloat16*)nullptr, (const __nv_bfloat16*)nullptr, 0, 0, 0

__global__ __launch_bounds__(NT)
void tc_proj_qk(const __nv_bfloat16* __restrict__ pool)
{
    __nv_bfloat16* p = (__nv_bfloat16*)pool;
    const int z = blockIdx.z;
    const int m0 = blockIdx.y * 128, n0 = blockIdx.x * 128;
    tc_body<0>(p + (z ? O_KH : O_QH), p + (z ? O_KL : O_QL),
               p + O_WH + z*EW, p + O_WL + z*EW, DD, DD, DD, NO2,
               nullptr, nullptr,
               p + (z ? O_KPH : O_QPH), p + (z ? O_KPL : O_QPL), DD, 0, m0, n0);
}

// Transposed projections: C[b][d][t] = sum_k W[d,k] * X[b,t,k]
__global__ __launch_bounds__(NT)
void tc_projT(const __nv_bfloat16* __restrict__ pool)
{
    __nv_bfloat16* p = (__nv_bfloat16*)pool;
    const int b = blockIdx.z / 3, w = blockIdx.z % 3;
    const int m0 = blockIdx.y * 128, n0 = blockIdx.x * 128;
    const int widx = (w == 0) ? 3 : (w == 1) ? 4 : 2;   // qs2, ks2, vs
    const size_t xo = (w == 0) ? O_QH : (w == 1) ? O_KH : O_VH;
    const size_t xl = (w == 0) ? O_QL : (w == 1) ? O_KL : O_VL;
    const size_t co = (w == 0) ? O_Q2TH : (w == 1) ? O_K2TH : O_VPTH;
    const size_t cl = (w == 0) ? O_Q2TL : (w == 1) ? O_K2TL : O_VPTL;
    tc_body<0>(p + O_WH + widx*EW, p + O_WL + widx*EW,
               p + xo + (size_t)b*LL*DD, p + xl + (size_t)b*LL*DD, DD, DD, DD, NO2,
               nullptr, nullptr,
               p + co + (size_t)b*DD*LL, p + cl + (size_t)b*DD*LL, LL, 0, m0, n0);
}

__global__ __launch_bounds__(NT)
void tc_dual(const __nv_bfloat16* __restrict__ pool)
{
    __nv_bfloat16* p = (__nv_bfloat16*)pool;
    const int b = blockIdx.z >> 1, sel = blockIdx.z & 1;
    const int m0 = blockIdx.y * 128, n0 = blockIdx.x * 128;
    const size_t bo = sel ? O_K2TH : O_Q2TH, bl = sel ? O_K2TL : O_Q2TL;
    const size_t co = sel ? O_K2FH : O_Q2FH, cl = sel ? O_K2FL : O_Q2FL;
    tc_body<0>(p + O_FAH + (size_t)b*LL*LL, p + O_FAL + (size_t)b*LL*LL,
               p + bo + (size_t)b*DD*LL,    p + bl + (size_t)b*DD*LL, LL, LL, LL, NO2,
               nullptr, nullptr,
               p + co + (size_t)b*LL*DD, p + cl + (size_t)b*LL*DD, DD, 0, m0, n0);
}

__global__ __launch_bounds__(NT)
void tc_logits(const __nv_bfloat16* __restrict__ pool, const int* __restrict__ lens,
               float* __restrict__ attn)
{
    __nv_bfloat16* p = (__nv_bfloat16*)pool;
    const int b = blockIdx.z;
    const size_t od = (size_t)b * LL * DD;
    const int m0 = blockIdx.y * 128, n0 = blockIdx.x * 128;
    tc_body<2>(p + O_QPH + od, p + O_QPL + od, p + O_KPH + od, p + O_KPL + od, DD, DD, DD,
               p + O_Q2FH + od, p + O_Q2FL + od, p + O_K2FH + od, p + O_K2FL + od, DD, DD, DD,
               attn + (size_t)b*LL*LL, nullptr,
               p + O_ATH + (size_t)b*LL*LL, p + O_ATL + (size_t)b*LL*LL,
               LL, lens[b], m0, n0);
}

__global__ __launch_bounds__(NT)
void tc_av(const __nv_bfloat16* __restrict__ pool)
{
    __nv_bfloat16* p = (__nv_bfloat16*)pool;
    const int b = blockIdx.z;
    const int m0 = blockIdx.y * 128, n0 = blockIdx.x * 128;
    tc_body<0>(p + O_ATH + (size_t)b*LL*LL, p + O_ATL + (size_t)b*LL*LL,
               p + O_VPTH + (size_t)b*DD*LL, p + O_VPTL + (size_t)b*DD*LL, LL, LL, LL, NO2,
               nullptr, nullptr,
               p + O_OVH + (size_t)b*LL*DD, p + O_OVL + (size_t)b*LL*DD, DD, 0, m0, n0);
}

__global__ __launch_bounds__(NT)
void tc_fc(const __nv_bfloat16* __restrict__ pool, const float* __restrict__ q,
           float* __restrict__ out)
{
    __nv_bfloat16* p = (__nv_bfloat16*)pool;
    const int m0 = blockIdx.y * 128, n0 = blockIdx.x * 128;
    tc_body<1>(p + O_OVH, p + O_OVL, p + O_WH + 5*EW, p + O_WL + 5*EW, DD, DD, DD, NO2,
               out, q, nullptr, nullptr, DD, 0, m0, n0);
}

// ---------------------------------------------------------------------------
// Conversion kernels (fp32 -> bf16 hi/lo)
// ---------------------------------------------------------------------------
__global__ __launch_bounds__(256)
void convert_qkv(const float* __restrict__ q, const float* __restrict__ k,
                 const float* __restrict__ v, __nv_bfloat16* __restrict__ pool)
{
    const int z = blockIdx.y;
    const float* s = (z == 0) ? q : (z == 1) ? k : v;
    __nv_bfloat16* h = pool + ((z == 0) ? O_QH : (z == 1) ? O_KH : O_VH);
    __nv_bfloat16* l = pool + ((z == 0) ? O_QL : (z == 1) ? O_KL : O_VL);
    const int i = blockIdx.x * 256 + threadIdx.x;
    float4 a = ((const float4*)s)[i];
    __nv_bfloat162 h01, l01, h23, l23;
    split2(a.x, a.y, h01, l01);
    split2(a.z, a.w, h23, l23);
    ((__nv_bfloat162*)h)[2*i]   = h01;
    ((__nv_bfloat162*)h)[2*i+1] = h23;
    ((__nv_bfloat162*)l)[2*i]   = l01;
    ((__nv_bfloat162*)l)[2*i+1] = l23;
}

__global__ __launch_bounds__(256)
void convert_w(const float* w0, const float* w1, const float* w2,
               const float* w3, const float* w4, const float* w5,
               __nv_bfloat16* __restrict__ pool)
{
    const int z = blockIdx.y;
    const float* s = (z==0)?w0:(z==1)?w1:(z==2)?w2:(z==3)?w3:(z==4)?w4:w5;
    __nv_bfloat16* h = pool + O_WH + (size_t)z*EW;
    __nv_bfloat16* l = pool + O_WL + (size_t)z*EW;
    const int i = blockIdx.x * 256 + threadIdx.x;
    float4 a = ((const float4*)s)[i];
    __nv_bfloat162 h01, l01, h23, l23;
    split2(a.x, a.y, h01, l01);
    split2(a.z, a.w, h23, l23);
    ((__nv_bfloat162*)h)[2*i]   = h01;
    ((__nv_bfloat162*)h)[2*i+1] = h23;
    ((__nv_bfloat162*)l)[2*i]   = l01;
    ((__nv_bfloat162*)l)[2*i+1] = l23;
}

// ---------------------------------------------------------------------------
// fa kernel: x[b] cached in smem, warp per row, writes bf16 hi/lo
// ---------------------------------------------------------------------------
__global__ __launch_bounds__(256)
void fa_kernel(const float* __restrict__ x, const float* __restrict__ fi,
               const int* __restrict__ lens, __nv_bfloat16* __restrict__ pool)
{
    __shared__ float xs[LL*FF];
    __shared__ float fis[FF];
    const int blk = blockIdx.x;
    const int b = blk >> 5, rb = blk & 31;
    const int tid = threadIdx.x;
    const float* xb = x + (size_t)b * LL * FF;
    for (int i = tid; i < LL*FF; i += 256) xs[i] = xb[i];
    if (tid < FF) fis[tid] = fi[tid];
    __syncthreads();
    const int len = lens[b];
    const int lane = tid & 31, warp = tid >> 5;
    __nv_bfloat16* fah = pool + O_FAH;
    __nv_bfloat16* fal = pool + O_FAL;

    #pragma unroll 1
    for (int r = 0; r < 4; r++) {
        const int i = rb*32 + warp*4 + r;
        float xi[FF];
        #pragma unroll
        for (int f = 0; f < FF; f++) xi[f] = xs[i*FF + f];
        float vals[32];
        float m = -INFINITY;
        #pragma unroll
        for (int it = 0; it < 32; it++) {
            const int j = lane + it*32;
            float s = 0.f;
            #pragma unroll
            for (int f = 0; f < FF; f++) s += fabsf(xi[f] - xs[j*FF + f]) * fis[f];
            s = (j < len) ? s : -INFINITY;
            vals[it] = s;
            m = fmaxf(m, s);
        }
        #pragma unroll
        for (int o = 16; o; o >>= 1) m = fmaxf(m, __shfl_xor_sync(~0u, m, o));
        float sum = 0.f;
        #pragma unroll
        for (int it = 0; it < 32; it++) {
            float e = expf(vals[it] - m);
            vals[it] = e;
            sum += e;
        }
        #pragma unroll
        for (int o = 16; o; o >>= 1) sum += __shfl_xor_sync(~0u, sum, o);
        const float inv = 1.f / sum;
        const size_t ro = ((size_t)b*LL + i) * LL;
        #pragma unroll
        for (int it = 0; it < 32; it++) {
            const int j = lane + it*32;
            const float f = vals[it] * inv;
            const __nv_bfloat16 h = __float2bfloat16(f);
            fah[ro + j] = h;
            fal[ro + j] = __float2bfloat16(f - __bfloat162float(h));
        }
    }
}

// ---------------------------------------------------------------------------
// LayerNorm
// ---------------------------------------------------------------------------
__global__ __launch_bounds__(256)
void ln_kernel(const float* __restrict__ in, const float* __restrict__ gamma,
               const float* __restrict__ beta, float* __restrict__ out)
{
    const int row = blockIdx.x;
    const int t = threadIdx.x;
    __shared__ float red[256];
    const float v = in[(size_t)row*DD + t];
    red[t] = v; __syncthreads();
    for (int s = 128; s > 0; s >>= 1) {
        if (t < s) red[t] += red[t+s];
        __syncthreads();
    }
    const float mean = red[0] * (1.0f/DD);
    __syncthreads();
    const float d = v - mean;
    red[t] = d * d; __syncthreads();
    for (int s = 128; s > 0; s >>= 1) {
        if (t < s) red[t] += red[t+s];
        __syncthreads();
    }
    const float var = red[0] * (1.0f/DD);
    out[(size_t)row*DD + t] = d * rsqrtf(var + LN_EPS) * gamma[t] + beta[t];
}

// ---------------------------------------------------------------------------
// Host launch
// ---------------------------------------------------------------------------
extern "C" void kernel_launch(void* const* d_in, const int* in_sizes, int n_in,
                              void* d_out, int out_size)
{
    int li = -1;
    for (int i = 0; i < n_in; i++) if (in_sizes[i] == BB) { li = i; break; }

    const float* q = (const float*)d_in[0];
    const float* k = (const float*)d_in[1];
    const float* v = (const float*)d_in[2];
    const float* x = (const float*)d_in[3];
    const int* lens;
    const float *w_qs, *w_ks, *w_vs, *w_qs2, *w_ks2, *w_fc, *fi, *gamma, *beta;
    if (li == 4) {
        lens  = (const int*)d_in[4];
        w_qs  = (const float*)d_in[5];  w_ks  = (const float*)d_in[6];
        w_vs  = (const float*)d_in[7];  w_qs2 = (const float*)d_in[8];
        w_ks2 = (const float*)d_in[9];  w_fc  = (const float*)d_in[10];
        fi    = (const float*)d_in[11]; gamma = (const float*)d_in[12];
        beta  = (const float*)d_in[13];
    } else {
        w_qs  = (const float*)d_in[4];  w_ks  = (const float*)d_in[5];
        w_vs  = (const float*)d_in[6];  w_qs2 = (const float*)d_in[7];
        w_ks2 = (const float*)d_in[8];  w_fc  = (const float*)d_in[9];
        fi    = (const float*)d_in[10]; gamma = (const float*)d_in[11];
        beta  = (const float*)d_in[12]; lens  = (const int*)d_in[13];
    }

    __nv_bfloat16* pool;
    float *fc, *attn_scratch;
    cudaGetSymbolAddress((void**)&pool, g_pool);
    cudaGetSymbolAddress((void**)&fc, g_fc);
    cudaGetSymbolAddress((void**)&attn_scratch, g_attn_scratch);

    const size_t OUT_ELEMS  = (size_t)BB*LL*DD;
    const size_t ATTN_ELEMS = (size_t)BB*LL*LL;
    float* attn = ((size_t)out_size >= OUT_ELEMS + ATTN_ELEMS)
                ? (float*)d_out + OUT_ELEMS
                : attn_scratch;

    cudaFuncSetAttribute(tc_proj_qk, cudaFuncAttributeMaxDynamicSharedMemorySize, SMEM_DYN);
    cudaFuncSetAttribute(tc_projT,   cudaFuncAttributeMaxDynamicSharedMemorySize, SMEM_DYN);
    cudaFuncSetAttribute(tc_dual,    cudaFuncAttributeMaxDynamicSharedMemorySize, SMEM_DYN);
    cudaFuncSetAttribute(tc_logits,  cudaFuncAttributeMaxDynamicSharedMemorySize, SMEM_DYN);
    cudaFuncSetAttribute(tc_av,      cudaFuncAttributeMaxDynamicSharedMemorySize, SMEM_DYN);
    cudaFuncSetAttribute(tc_fc,      cudaFuncAttributeMaxDynamicSharedMemorySize, SMEM_DYN);

    const int M = BB * LL;  // 8192
    dim3 blk(NT);
    dim3 blk256(256);

    // fp32 -> bf16 hi/lo conversions
    convert_qkv<<<dim3(E2M/4/256, 3), blk256>>>(q, k, v, pool);
    convert_w<<<dim3(EW/4/256, 6), blk256>>>(w_qs, w_ks, w_vs, w_qs2, w_ks2, w_fc, pool);

    // feature-affinity softmax -> fa hi/lo
    fa_kernel<<<BB*32, blk256>>>(x, fi, lens, pool);

    // qp, kp projections
    tc_proj_qk<<<dim3(DD/128, M/128, 2), blk, SMEM_DYN>>>(pool);

    // transposed projections q2t/k2t/vpt
    tc_projT<<<dim3(LL/128, DD/128, 3*BB), blk, SMEM_DYN>>>(pool);

    // q2f = fa@q2, k2f = fa@k2
    tc_dual<<<dim3(DD/128, LL/128, BB*2), blk, SMEM_DYN>>>(pool);

    // logits + mask + tanh -> attn fp32 + hi/lo
    tc_logits<<<dim3(LL/128, LL/128, BB), blk, SMEM_DYN>>>(pool, lens, attn);

    // out = attn @ vp
    tc_av<<<dim3(DD/128, LL/128, BB), blk, SMEM_DYN>>>(pool);

    // fc + residual, then layernorm
    tc_fc<<<dim3(DD/128, M/128, 1), blk, SMEM_DYN>>>(pool, q, fc);
    ln_kernel<<<M, blk256>>>(fc, gamma, beta, (float*)d_out);
}

// round 8
// speedup vs baseline: 1.5131x; 1.5131x over previous
#include <cuda_runtime.h>
#include <cuda_bf16.h>
#include <math.h>
#include <stdint.h>

// Problem constants
#define BB 8
#define LL 1024
#define DD 256
#define FF 11
#define TEMP_INV (1.0f/16.0f)
#define LN_EPS 1e-6f

// GEMM config: 128x128 CTA tile, K-slab 64, 16 warps (4m x 4n), warp tile 32x32
#define SLAB 64
#define TB 16384                // one 128x64 bf16 tile
#define BUFB (4*TB)             // AH AL BH BL
#define SMEM_DYN (2*BUFB)       // 131072 (double buffered)
#define NT 512                  // threads per CTA

// ---------------------------------------------------------------------------
// Scratch
// ---------------------------------------------------------------------------
__device__ float g_qp [BB*LL*DD];
__device__ float g_kp [BB*LL*DD];
__device__ float g_q2t[BB*LL*DD];   // [b][d][t]
__device__ float g_k2t[BB*LL*DD];
__device__ float g_vpt[BB*LL*DD];
__device__ float g_q2f[BB*LL*DD];
__device__ float g_k2f[BB*LL*DD];
__device__ float g_ov [BB*LL*DD];
__device__ float g_fc [BB*LL*DD];
__device__ float g_fa [(size_t)BB*LL*LL];
__device__ float g_attn_scratch[(size_t)BB*LL*LL];

// ---------------------------------------------------------------------------
// Helpers
// ---------------------------------------------------------------------------
__device__ __forceinline__ uint32_t smem_u32(const void* p) {
    uint32_t a;
    asm("{ .reg .u64 t; cvta.to.shared.u64 t, %1; cvt.u32.u64 %0, t; }"
        : "=r"(a) : "l"(p));
    return a;
}

__device__ __forceinline__ void ldsm_x4(uint32_t* r, uint32_t a) {
    asm volatile("ldmatrix.sync.aligned.m8n8.x4.shared.b16 {%0,%1,%2,%3}, [%4];"
        : "=r"(r[0]), "=r"(r[1]), "=r"(r[2]), "=r"(r[3]) : "r"(a));
}

__device__ __forceinline__ void mma16816(float* c, const uint32_t* a, const uint32_t* b) {
    asm volatile("mma.sync.aligned.m16n8k16.row.col.f32.bf16.bf16.f32 "
        "{%0,%1,%2,%3}, {%4,%5,%6,%7}, {%8,%9}, {%0,%1,%2,%3};"
        : "+f"(c[0]), "+f"(c[1]), "+f"(c[2]), "+f"(c[3])
        : "r"(a[0]), "r"(a[1]), "r"(a[2]), "r"(a[3]), "r"(b[0]), "r"(b[1]));
}

// Load a 128x64 fp32 tile into registers (4 float4 per thread, 512 threads).
__device__ __forceinline__
void ld_tile(const float* __restrict__ src, int r0, int ld, int k0,
             float4* v, int tid)
{
    #pragma unroll
    for (int i = 0; i < 4; i++) {
        int f = tid + (i << 9);
        int row = f >> 4, c4 = f & 15;
        v[i] = *(const float4*)(src + (size_t)(r0 + row) * ld + k0 + (c4 << 2));
    }
}

// Split registers into bf16 hi/lo and store SW128-swizzled into smem.
__device__ __forceinline__
void st_tile(const float4* v, char* smem, uint32_t hiOff, uint32_t loOff, int tid)
{
    #pragma unroll
    for (int i = 0; i < 4; i++) {
        int f = tid + (i << 9);
        int row = f >> 4, c4 = f & 15;
        float4 a = v[i];
        __nv_bfloat162 h01 = __floats2bfloat162_rn(a.x, a.y);
        __nv_bfloat162 h23 = __floats2bfloat162_rn(a.z, a.w);
        float rx = a.x - __bfloat162float(h01.x);
        float ry = a.y - __bfloat162float(h01.y);
        float rz = a.z - __bfloat162float(h23.x);
        float rw = a.w - __bfloat162float(h23.y);
        __nv_bfloat162 l01 = __floats2bfloat162_rn(rx, ry);
        __nv_bfloat162 l23 = __floats2bfloat162_rn(rz, rw);
        uint32_t byte = (row << 7) + (c4 << 3);
        uint32_t sw = byte ^ ((byte >> 3) & 0x70);
        *(uint2*)(smem + hiOff + sw) = make_uint2(*(uint32_t*)&h01, *(uint32_t*)&h23);
        *(uint2*)(smem + loOff + sw) = make_uint2(*(uint32_t*)&l01, *(uint32_t*)&l23);
    }
}

// ---------------------------------------------------------------------------
// bf16x3 mma.sync GEMM body. NT: C[m,n] = sum_k A[m,k]*B[n,k] over
// (A1,B1,kext1,ld1) then (A2,B2,kext2,ld2). kext may be < ld (masked K).
// MODE: 0 plain, 1 +add residual, 2 tanh(acc/16) w/ col mask
// ---------------------------------------------------------------------------
template<int MODE>
__device__ __forceinline__
void tc_body(const float* __restrict__ A1, const float* __restrict__ B1,
             int k1, int ld1,
             const float* __restrict__ A2, const float* __restrict__ B2,
             int k2, int ld2,
             float* __restrict__ C, const float* __restrict__ add,
             int ldc, int len, int m0, int n0)
{
    extern __shared__ char smem[];
    const uint32_t sb = smem_u32(smem);
    const int tid = threadIdx.x;
    const int lane = tid & 31, wid = tid >> 5;
    const int wm = wid & 3, wn = wid >> 2;

    float acc[2][4][4] = {};

    // ldmatrix lane addressing (128B rows, SW128-style XOR)
    const int a_row = wm * 32 + (lane & 15);
    const uint32_t a_colp = (lane >> 4) << 4;
    const uint32_t a_xor = (uint32_t)(a_row & 7) << 4;
    const int b_row = wn * 32 + ((lane >> 4) << 3) + (lane & 7);
    const uint32_t b_colp = ((lane >> 3) & 1) << 4;
    const uint32_t b_xor = (uint32_t)(b_row & 7) << 4;

    const int n1 = k1 / SLAB;
    const int nslabs = n1 + (A2 ? k2 / SLAB : 0);

    float4 av[4], bv[4];
    // prologue: slab 0
    ld_tile(A1, m0, ld1, 0, av, tid);
    ld_tile(B1, n0, ld1, 0, bv, tid);
    st_tile(av, smem, 0, TB, tid);
    st_tile(bv, smem, 2*TB, 3*TB, tid);
    __syncthreads();

    for (int s = 0; s < nslabs; s++) {
        const uint32_t bo = (s & 1) * BUFB;
        const uint32_t bn = bo ^ BUFB;
        const bool has = (s + 1) < nslabs;
        const float *An = A1, *Bn = B1; int ldn = ld1, k0n = 0;
        if (has) {
            int sn = s + 1;
            if (sn < n1) { An = A1; Bn = B1; ldn = ld1; k0n = sn * SLAB; }
            else         { An = A2; Bn = B2; ldn = ld2; k0n = (sn - n1) * SLAB; }
        }

        #pragma unroll
        for (int kk = 0; kk < 4; kk++) {
            if (kk == 0 && has) ld_tile(An, m0, ldn, k0n, av, tid);
            if (kk == 2 && has) {
                st_tile(av, smem, bn, bn + TB, tid);
                ld_tile(Bn, n0, ldn, k0n, bv, tid);
            }
            if (kk == 3 && has) st_tile(bv, smem, bn + 2*TB, bn + 3*TB, tid);

            const uint32_t kb = kk << 5;
            uint32_t bH[8], bL[8];
            {
                uint32_t r = (uint32_t)b_row << 7;
                uint32_t c = (kb + b_colp) ^ b_xor;
                ldsm_x4(bH + 0, sb + bo + 2*TB + r + c);
                ldsm_x4(bH + 4, sb + bo + 2*TB + r + 2048 + c);
                ldsm_x4(bL + 0, sb + bo + 3*TB + r + c);
                ldsm_x4(bL + 4, sb + bo + 3*TB + r + 2048 + c);
            }
            #pragma unroll
            for (int mt = 0; mt < 2; mt++) {
                uint32_t aH[4], aL[4];
                uint32_t r = (uint32_t)(a_row + mt*16) << 7;
                uint32_t c = (kb + a_colp) ^ a_xor;
                ldsm_x4(aH, sb + bo + r + c);
                ldsm_x4(aL, sb + bo + TB + r + c);
                #pragma unroll
                for (int nt = 0; nt < 4; nt++) {
                    mma16816(acc[mt][nt], aH, bH + nt*2);
                    mma16816(acc[mt][nt], aH, bL + nt*2);
                    mma16816(acc[mt][nt], aL, bH + nt*2);
                }
            }
        }
        if (has) __syncthreads();
    }

    // epilogue
    const int mg = m0 + wm * 32;
    const int ng = n0 + wn * 32;
    const int rq = lane >> 2;
    const int cq = (lane & 3) << 1;
    #pragma unroll
    for (int mt = 0; mt < 2; mt++) {
        #pragma unroll
        for (int nt = 0; nt < 4; nt++) {
            const float* a4 = acc[mt][nt];
            const int r0 = mg + mt*16 + rq, r1 = r0 + 8;
            const int c0 = ng + nt*8 + cq;
            if (MODE == 0) {
                *(float2*)(C + (size_t)r0*ldc + c0) = make_float2(a4[0], a4[1]);
                *(float2*)(C + (size_t)r1*ldc + c0) = make_float2(a4[2], a4[3]);
            } else if (MODE == 1) {
                float2 x0 = *(const float2*)(add + (size_t)r0*ldc + c0);
                float2 x1 = *(const float2*)(add + (size_t)r1*ldc + c0);
                *(float2*)(C + (size_t)r0*ldc + c0) = make_float2(a4[0]+x0.x, a4[1]+x0.y);
                *(float2*)(C + (size_t)r1*ldc + c0) = make_float2(a4[2]+x1.x, a4[3]+x1.y);
            } else {
                float2 v0, v1;
                v0.x = (c0   < len) ? tanhf(a4[0]*TEMP_INV) : 0.f;
                v0.y = (c0+1 < len) ? tanhf(a4[1]*TEMP_INV) : 0.f;
                v1.x = (c0   < len) ? tanhf(a4[2]*TEMP_INV) : 0.f;
                v1.y = (c0+1 < len) ? tanhf(a4[3]*TEMP_INV) : 0.f;
                *(float2*)(C + (size_t)r0*ldc + c0) = v0;
                *(float2*)(C + (size_t)r1*ldc + c0) = v1;
            }
        }
    }
}

// ---------------------------------------------------------------------------
// Stage kernels
// ---------------------------------------------------------------------------
__global__ __launch_bounds__(NT, 1)
void tc_proj_qk(const float* __restrict__ q, const float* __restrict__ k,
                const float* __restrict__ w_qs, const float* __restrict__ w_ks,
                float* __restrict__ qp, float* __restrict__ kp)
{
    const int m0 = blockIdx.y * 128, n0 = blockIdx.x * 128;
    if (blockIdx.z == 0)
        tc_body<0>(q, w_qs, DD, DD, nullptr, nullptr, 0, 0, qp, nullptr, DD, 0, m0, n0);
    else
        tc_body<0>(k, w_ks, DD, DD, nullptr, nullptr, 0, 0, kp, nullptr, DD, 0, m0, n0);
}

// Transposed projections: C_b = W (256xK) . X_b^T -> [256,1024] = [d][t]
__global__ __launch_bounds__(NT, 1)
void tc_projT(const float* __restrict__ q, const float* __restrict__ k,
              const float* __restrict__ v,
              const float* __restrict__ w_qs2, const float* __restrict__ w_ks2,
              const float* __restrict__ w_vs,
              float* __restrict__ q2t, float* __restrict__ k2t,
              float* __restrict__ vpt)
{
    const int b = blockIdx.z / 3, w = blockIdx.z % 3;
    const int m0 = blockIdx.y * 128, n0 = blockIdx.x * 128;
    const float* W; const float* X; float* C;
    if      (w == 0) { W = w_qs2; X = q; C = q2t; }
    else if (w == 1) { W = w_ks2; X = k; C = k2t; }
    else             { W = w_vs;  X = v; C = vpt; }
    tc_body<0>(W, X + (size_t)b*LL*DD, DD, DD, nullptr, nullptr, 0, 0,
               C + (size_t)b*DD*LL, nullptr, LL, 0, m0, n0);
}

// q2f = fa @ q2 (as NT with q2t), k2f = fa @ k2. K masked to ceil(len/64)*64.
__global__ __launch_bounds__(NT, 1)
void tc_dual(const float* __restrict__ fa, const float* __restrict__ q2t,
             const float* __restrict__ k2t, const int* __restrict__ lens,
             float* __restrict__ q2f, float* __restrict__ k2f)
{
    const int b = blockIdx.z >> 1, sel = blockIdx.z & 1;
    const int m0 = blockIdx.y * 128, n0 = blockIdx.x * 128;
    const int kmax = ((lens[b] + SLAB - 1) / SLAB) * SLAB;   // fa cols >= len are 0
    const float* A = fa + (size_t)b * LL * LL;
    const float* B = (sel ? k2t : q2t) + (size_t)b * DD * LL;
    float* C = (sel ? k2f : q2f) + (size_t)b * LL * DD;
    tc_body<0>(A, B, kmax, LL, nullptr, nullptr, 0, 0, C, nullptr, DD, 0, m0, n0);
}

__global__ __launch_bounds__(NT, 1)
void tc_logits(const float* __restrict__ qp, const float* __restrict__ kp,
               const float* __restrict__ q2f, const float* __restrict__ k2f,
               const int* __restrict__ lens, float* __restrict__ attn)
{
    const int b = blockIdx.z;
    const size_t od = (size_t)b * LL * DD;
    const int m0 = blockIdx.y * 128, n0 = blockIdx.x * 128;
    const int len = lens[b];
    float* out = attn + (size_t)b * LL * LL;
    if (n0 >= len) {
        // whole n-tile masked: attn = 0, skip GEMM entirely
        const float4 z4 = make_float4(0.f, 0.f, 0.f, 0.f);
        for (int i = threadIdx.x; i < 128 * 32; i += NT) {
            int r = i >> 5, c4 = i & 31;
            *(float4*)(out + (size_t)(m0 + r) * LL + n0 + (c4 << 2)) = z4;
        }
        return;
    }
    tc_body<2>(qp + od, kp + od, DD, DD, q2f + od, k2f + od, DD, DD,
               out, nullptr, LL, len, m0, n0);
}

// out = attn @ vp. attn cols >= len are exactly 0 -> mask K.
__global__ __launch_bounds__(NT, 1)
void tc_av(const float* __restrict__ attn, const float* __restrict__ vpt,
           const int* __restrict__ lens, float* __restrict__ ov)
{
    const int b = blockIdx.z;
    const int m0 = blockIdx.y * 128, n0 = blockIdx.x * 128;
    const int kmax = ((lens[b] + SLAB - 1) / SLAB) * SLAB;
    tc_body<0>(attn + (size_t)b * LL * LL, vpt + (size_t)b * DD * LL, kmax, LL,
               nullptr, nullptr, 0, 0, ov + (size_t)b * LL * DD, nullptr, DD, 0, m0, n0);
}

__global__ __launch_bounds__(NT, 1)
void tc_fc(const float* __restrict__ ov, const float* __restrict__ w_fc,
           const float* __restrict__ q, float* __restrict__ out)
{
    const int m0 = blockIdx.y * 128, n0 = blockIdx.x * 128;
    tc_body<1>(ov, w_fc, DD, DD, nullptr, nullptr, 0, 0, out, q, DD, 0, m0, n0);
}

// ---------------------------------------------------------------------------
// fa kernel: x[b] cached in smem, warp per row, fp32 output.
// grid: BB*32 blocks (b = blk>>5, 32 rows per block), 256 threads (8 warps x 4 rows)
// ---------------------------------------------------------------------------
__global__ __launch_bounds__(256)
void fa_kernel(const float* __restrict__ x, const float* __restrict__ fi,
               const int* __restrict__ lens, float* __restrict__ fa)
{
    __shared__ float xs[LL*FF];
    __shared__ float fis[FF];
    const int blk = blockIdx.x;
    const int b = blk >> 5, rb = blk & 31;
    const int tid = threadIdx.x;
    const float* xb = x + (size_t)b * LL * FF;
    for (int i = tid; i < LL*FF; i += 256) xs[i] = xb[i];
    if (tid < FF) fis[tid] = fi[tid];
    __syncthreads();
    const int len = lens[b];
    const int lane = tid & 31, warp = tid >> 5;

    #pragma unroll 1
    for (int r = 0; r < 4; r++) {
        const int i = rb*32 + warp*4 + r;
        float xi[FF];
        #pragma unroll
        for (int f = 0; f < FF; f++) xi[f] = xs[i*FF + f];
        float vals[32];
        float m = -INFINITY;
        #pragma unroll
        for (int it = 0; it < 32; it++) {
            const int j = lane + it*32;
            float s = 0.f;
            #pragma unroll
            for (int f = 0; f < FF; f++) s += fabsf(xi[f] - xs[j*FF + f]) * fis[f];
            s = (j < len) ? s : -INFINITY;
            vals[it] = s;
            m = fmaxf(m, s);
        }
        #pragma unroll
        for (int o = 16; o; o >>= 1) m = fmaxf(m, __shfl_xor_sync(~0u, m, o));
        float sum = 0.f;
        #pragma unroll
        for (int it = 0; it < 32; it++) {
            float e = expf(vals[it] - m);
            vals[it] = e;
            sum += e;
        }
        #pragma unroll
        for (int o = 16; o; o >>= 1) sum += __shfl_xor_sync(~0u, sum, o);
        const float inv = 1.f / sum;
        float* outp = fa + ((size_t)b*LL + i) * LL;
        #pragma unroll
        for (int it = 0; it < 32; it++)
            outp[lane + it*32] = vals[it] * inv;
    }
}

// ---------------------------------------------------------------------------
// LayerNorm
// ---------------------------------------------------------------------------
__global__ __launch_bounds__(256)
void ln_kernel(const float* __restrict__ in, const float* __restrict__ gamma,
               const float* __restrict__ beta, float* __restrict__ out)
{
    const int row = blockIdx.x;
    const int t = threadIdx.x;
    __shared__ float red[256];
    const float v = in[(size_t)row*DD + t];
    red[t] = v; __syncthreads();
    for (int s = 128; s > 0; s >>= 1) {
        if (t < s) red[t] += red[t+s];
        __syncthreads();
    }
    const float mean = red[0] * (1.0f/DD);
    __syncthreads();
    const float d = v - mean;
    red[t] = d * d; __syncthreads();
    for (int s = 128; s > 0; s >>= 1) {
        if (t < s) red[t] += red[t+s];
        __syncthreads();
    }
    const float var = red[0] * (1.0f/DD);
    out[(size_t)row*DD + t] = d * rsqrtf(var + LN_EPS) * gamma[t] + beta[t];
}

// ---------------------------------------------------------------------------
// Host launch
// ---------------------------------------------------------------------------
extern "C" void kernel_launch(void* const* d_in, const int* in_sizes, int n_in,
                              void* d_out, int out_size)
{
    int li = -1;
    for (int i = 0; i < n_in; i++) if (in_sizes[i] == BB) { li = i; break; }

    const float* q = (const float*)d_in[0];
    const float* k = (const float*)d_in[1];
    const float* v = (const float*)d_in[2];
    const float* x = (const float*)d_in[3];
    const int* lens;
    const float *w_qs, *w_ks, *w_vs, *w_qs2, *w_ks2, *w_fc, *fi, *gamma, *beta;
    if (li == 4) {
        lens  = (const int*)d_in[4];
        w_qs  = (const float*)d_in[5];  w_ks  = (const float*)d_in[6];
        w_vs  = (const float*)d_in[7];  w_qs2 = (const float*)d_in[8];
        w_ks2 = (const float*)d_in[9];  w_fc  = (const float*)d_in[10];
        fi    = (const float*)d_in[11]; gamma = (const float*)d_in[12];
        beta  = (const float*)d_in[13];
    } else {
        w_qs  = (const float*)d_in[4];  w_ks  = (const float*)d_in[5];
        w_vs  = (const float*)d_in[6];  w_qs2 = (const float*)d_in[7];
        w_ks2 = (const float*)d_in[8];  w_fc  = (const float*)d_in[9];
        fi    = (const float*)d_in[10]; gamma = (const float*)d_in[11];
        beta  = (const float*)d_in[12]; lens  = (const int*)d_in[13];
    }

    float *qp, *kp, *q2t, *k2t, *vpt, *q2f, *k2f, *ov, *fc, *fa, *attn_scratch;
    cudaGetSymbolAddress((void**)&qp,  g_qp);
    cudaGetSymbolAddress((void**)&kp,  g_kp);
    cudaGetSymbolAddress((void**)&q2t, g_q2t);
    cudaGetSymbolAddress((void**)&k2t, g_k2t);
    cudaGetSymbolAddress((void**)&vpt, g_vpt);
    cudaGetSymbolAddress((void**)&q2f, g_q2f);
    cudaGetSymbolAddress((void**)&k2f, g_k2f);
    cudaGetSymbolAddress((void**)&ov,  g_ov);
    cudaGetSymbolAddress((void**)&fc,  g_fc);
    cudaGetSymbolAddress((void**)&fa,  g_fa);
    cudaGetSymbolAddress((void**)&attn_scratch, g_attn_scratch);

    const size_t OUT_ELEMS  = (size_t)BB*LL*DD;
    const size_t ATTN_ELEMS = (size_t)BB*LL*LL;
    float* attn = ((size_t)out_size >= OUT_ELEMS + ATTN_ELEMS)
                ? (float*)d_out + OUT_ELEMS
                : attn_scratch;

    cudaFuncSetAttribute(tc_proj_qk, cudaFuncAttributeMaxDynamicSharedMemorySize, SMEM_DYN);
    cudaFuncSetAttribute(tc_projT,   cudaFuncAttributeMaxDynamicSharedMemorySize, SMEM_DYN);
    cudaFuncSetAttribute(tc_dual,    cudaFuncAttributeMaxDynamicSharedMemorySize, SMEM_DYN);
    cudaFuncSetAttribute(tc_logits,  cudaFuncAttributeMaxDynamicSharedMemorySize, SMEM_DYN);
    cudaFuncSetAttribute(tc_av,      cudaFuncAttributeMaxDynamicSharedMemorySize, SMEM_DYN);
    cudaFuncSetAttribute(tc_fc,      cudaFuncAttributeMaxDynamicSharedMemorySize, SMEM_DYN);

    const int M = BB * LL;  // 8192
    dim3 blk(NT);
    dim3 blk256(256);

    // qp, kp projections: [8192,256] x [256,256]
    tc_proj_qk<<<dim3(DD/128, M/128, 2), blk, SMEM_DYN>>>(q, k, w_qs, w_ks, qp, kp);

    // transposed projections q2t/k2t/vpt: per batch [256,256] x [1024,256]^T
    tc_projT<<<dim3(LL/128, DD/128, 3*BB), blk, SMEM_DYN>>>(
        q, k, v, w_qs2, w_ks2, w_vs, q2t, k2t, vpt);

    // feature-affinity softmax (warp-per-row, x cached in smem)
    fa_kernel<<<BB*32, blk256>>>(x, fi, lens, fa);

    // q2f = fa@q2, k2f = fa@k2 (K masked by len)
    tc_dual<<<dim3(DD/128, LL/128, BB*2), blk, SMEM_DYN>>>(fa, q2t, k2t, lens, q2f, k2f);

    // logits + mask + tanh (fully-masked n-tiles skipped)
    tc_logits<<<dim3(LL/128, LL/128, BB), blk, SMEM_DYN>>>(qp, kp, q2f, k2f, lens, attn);

    // out = attn @ vp (K masked by len)
    tc_av<<<dim3(DD/128, LL/128, BB), blk, SMEM_DYN>>>(attn, vpt, lens, ov);

    // fc + residual, then layernorm
    tc_fc<<<dim3(DD/128, M/128, 1), blk, SMEM_DYN>>>(ov, w_fc, q, fc);
    ln_kernel<<<M, blk256>>>(fc, gamma, beta, (float*)d_out);
}

// round 9
// speedup vs baseline: 1.6980x; 1.1222x over previous
#include <cuda_runtime.h>
#include <cuda_bf16.h>
#include <math.h>
#include <stdint.h>

// Problem constants
#define BB 8
#define LL 1024
#define DD 256
#define FF 11
#define TEMP_INV (1.0f/16.0f)
#define LN_EPS 1e-6f

// GEMM config: 128x128 CTA tile, K-slab 64, 16 warps (4m x 4n), warp tile 32x32
#define SLAB 64
#define TB 16384                // one 128x64 bf16 tile
#define BUFB (4*TB)             // AH AL BH BL
#define SMEM_DYN (2*BUFB)       // 131072 (double buffered)
#define NT 512                  // threads per CTA

// ---------------------------------------------------------------------------
// Scratch
// ---------------------------------------------------------------------------
__device__ float g_qp [BB*LL*DD];
__device__ float g_kp [BB*LL*DD];
__device__ float g_q2t[BB*LL*DD];   // [b][d][t]
__device__ float g_k2t[BB*LL*DD];
__device__ float g_vpt[BB*LL*DD];
__device__ float g_q2f[BB*LL*DD];
__device__ float g_k2f[BB*LL*DD];
__device__ float g_ov [BB*LL*DD];
__device__ float g_fc [BB*LL*DD];
__device__ float g_fa [(size_t)BB*LL*LL];
__device__ float g_attn_scratch[(size_t)BB*LL*LL];

// ---------------------------------------------------------------------------
// Helpers
// ---------------------------------------------------------------------------
__device__ __forceinline__ uint32_t smem_u32(const void* p) {
    uint32_t a;
    asm("{ .reg .u64 t; cvta.to.shared.u64 t, %1; cvt.u32.u64 %0, t; }"
        : "=r"(a) : "l"(p));
    return a;
}

__device__ __forceinline__ void ldsm_x4(uint32_t* r, uint32_t a) {
    asm volatile("ldmatrix.sync.aligned.m8n8.x4.shared.b16 {%0,%1,%2,%3}, [%4];"
        : "=r"(r[0]), "=r"(r[1]), "=r"(r[2]), "=r"(r[3]) : "r"(a));
}

__device__ __forceinline__ void mma16816(float* c, const uint32_t* a, const uint32_t* b) {
    asm volatile("mma.sync.aligned.m16n8k16.row.col.f32.bf16.bf16.f32 "
        "{%0,%1,%2,%3}, {%4,%5,%6,%7}, {%8,%9}, {%0,%1,%2,%3};"
        : "+f"(c[0]), "+f"(c[1]), "+f"(c[2]), "+f"(c[3])
        : "r"(a[0]), "r"(a[1]), "r"(a[2]), "r"(a[3]), "r"(b[0]), "r"(b[1]));
}

// Load a 128x64 fp32 tile into registers (4 float4 per thread, 512 threads).
__device__ __forceinline__
void ld_tile(const float* __restrict__ src, int r0, int ld, int k0,
             float4* v, int tid)
{
    #pragma unroll
    for (int i = 0; i < 4; i++) {
        int f = tid + (i << 9);
        int row = f >> 4, c4 = f & 15;
        v[i] = *(const float4*)(src + (size_t)(r0 + row) * ld + k0 + (c4 << 2));
    }
}

// Split registers into bf16 hi/lo and store SW128-swizzled into smem.
__device__ __forceinline__
void st_tile(const float4* v, char* smem, uint32_t hiOff, uint32_t loOff, int tid)
{
    #pragma unroll
    for (int i = 0; i < 4; i++) {
        int f = tid + (i << 9);
        int row = f >> 4, c4 = f & 15;
        float4 a = v[i];
        __nv_bfloat162 h01 = __floats2bfloat162_rn(a.x, a.y);
        __nv_bfloat162 h23 = __floats2bfloat162_rn(a.z, a.w);
        float rx = a.x - __bfloat162float(h01.x);
        float ry = a.y - __bfloat162float(h01.y);
        float rz = a.z - __bfloat162float(h23.x);
        float rw = a.w - __bfloat162float(h23.y);
        __nv_bfloat162 l01 = __floats2bfloat162_rn(rx, ry);
        __nv_bfloat162 l23 = __floats2bfloat162_rn(rz, rw);
        uint32_t byte = (row << 7) + (c4 << 3);
        uint32_t sw = byte ^ ((byte >> 3) & 0x70);
        *(uint2*)(smem + hiOff + sw) = make_uint2(*(uint32_t*)&h01, *(uint32_t*)&h23);
        *(uint2*)(smem + loOff + sw) = make_uint2(*(uint32_t*)&l01, *(uint32_t*)&l23);
    }
}

// ---------------------------------------------------------------------------
// bf16x3 mma.sync GEMM body. NT: C[m,n] = sum_k A[m,k]*B[n,k] over
// (A1,B1,kext1,ld1) then (A2,B2,kext2,ld2). kext may be < ld (masked K).
// MODE: 0 plain, 1 +add residual, 2 tanh(acc/16) w/ col mask
// ---------------------------------------------------------------------------
template<int MODE>
__device__ __forceinline__
void tc_body(const float* __restrict__ A1, const float* __restrict__ B1,
             int k1, int ld1,
             const float* __restrict__ A2, const float* __restrict__ B2,
             int k2, int ld2,
             float* __restrict__ C, const float* __restrict__ add,
             int ldc, int len, int m0, int n0)
{
    extern __shared__ char smem[];
    const uint32_t sb = smem_u32(smem);
    const int tid = threadIdx.x;
    const int lane = tid & 31, wid = tid >> 5;
    const int wm = wid & 3, wn = wid >> 2;

    float acc[2][4][4] = {};

    // ldmatrix lane addressing (128B rows, SW128-style XOR)
    const int a_row = wm * 32 + (lane & 15);
    const uint32_t a_colp = (lane >> 4) << 4;
    const uint32_t a_xor = (uint32_t)(a_row & 7) << 4;
    const int b_row = wn * 32 + ((lane >> 4) << 3) + (lane & 7);
    const uint32_t b_colp = ((lane >> 3) & 1) << 4;
    const uint32_t b_xor = (uint32_t)(b_row & 7) << 4;

    const int n1 = k1 / SLAB;
    const int nslabs = n1 + (A2 ? k2 / SLAB : 0);

    float4 av[4], bv[4];
    // prologue: slab 0
    ld_tile(A1, m0, ld1, 0, av, tid);
    ld_tile(B1, n0, ld1, 0, bv, tid);
    st_tile(av, smem, 0, TB, tid);
    st_tile(bv, smem, 2*TB, 3*TB, tid);
    __syncthreads();

    for (int s = 0; s < nslabs; s++) {
        const uint32_t bo = (s & 1) * BUFB;
        const uint32_t bn = bo ^ BUFB;
        const bool has = (s + 1) < nslabs;
        const float *An = A1, *Bn = B1; int ldn = ld1, k0n = 0;
        if (has) {
            int sn = s + 1;
            if (sn < n1) { An = A1; Bn = B1; ldn = ld1; k0n = sn * SLAB; }
            else         { An = A2; Bn = B2; ldn = ld2; k0n = (sn - n1) * SLAB; }
        }

        #pragma unroll
        for (int kk = 0; kk < 4; kk++) {
            if (kk == 0 && has) ld_tile(An, m0, ldn, k0n, av, tid);
            if (kk == 2 && has) {
                st_tile(av, smem, bn, bn + TB, tid);
                ld_tile(Bn, n0, ldn, k0n, bv, tid);
            }
            if (kk == 3 && has) st_tile(bv, smem, bn + 2*TB, bn + 3*TB, tid);

            const uint32_t kb = kk << 5;
            uint32_t bH[8], bL[8];
            {
                uint32_t r = (uint32_t)b_row << 7;
                uint32_t c = (kb + b_colp) ^ b_xor;
                ldsm_x4(bH + 0, sb + bo + 2*TB + r + c);
                ldsm_x4(bH + 4, sb + bo + 2*TB + r + 2048 + c);
                ldsm_x4(bL + 0, sb + bo + 3*TB + r + c);
                ldsm_x4(bL + 4, sb + bo + 3*TB + r + 2048 + c);
            }
            #pragma unroll
            for (int mt = 0; mt < 2; mt++) {
                uint32_t aH[4], aL[4];
                uint32_t r = (uint32_t)(a_row + mt*16) << 7;
                uint32_t c = (kb + a_colp) ^ a_xor;
                ldsm_x4(aH, sb + bo + r + c);
                ldsm_x4(aL, sb + bo + TB + r + c);
                #pragma unroll
                for (int nt = 0; nt < 4; nt++) {
                    mma16816(acc[mt][nt], aH, bH + nt*2);
                    mma16816(acc[mt][nt], aH, bL + nt*2);
                    mma16816(acc[mt][nt], aL, bH + nt*2);
                }
            }
        }
        if (has) __syncthreads();
    }

    // epilogue
    const int mg = m0 + wm * 32;
    const int ng = n0 + wn * 32;
    const int rq = lane >> 2;
    const int cq = (lane & 3) << 1;
    #pragma unroll
    for (int mt = 0; mt < 2; mt++) {
        #pragma unroll
        for (int nt = 0; nt < 4; nt++) {
            const float* a4 = acc[mt][nt];
            const int r0 = mg + mt*16 + rq, r1 = r0 + 8;
            const int c0 = ng + nt*8 + cq;
            if (MODE == 0) {
                *(float2*)(C + (size_t)r0*ldc + c0) = make_float2(a4[0], a4[1]);
                *(float2*)(C + (size_t)r1*ldc + c0) = make_float2(a4[2], a4[3]);
            } else if (MODE == 1) {
                float2 x0 = *(const float2*)(add + (size_t)r0*ldc + c0);
                float2 x1 = *(const float2*)(add + (size_t)r1*ldc + c0);
                *(float2*)(C + (size_t)r0*ldc + c0) = make_float2(a4[0]+x0.x, a4[1]+x0.y);
                *(float2*)(C + (size_t)r1*ldc + c0) = make_float2(a4[2]+x1.x, a4[3]+x1.y);
            } else {
                float2 v0, v1;
                v0.x = (c0   < len) ? tanhf(a4[0]*TEMP_INV) : 0.f;
                v0.y = (c0+1 < len) ? tanhf(a4[1]*TEMP_INV) : 0.f;
                v1.x = (c0   < len) ? tanhf(a4[2]*TEMP_INV) : 0.f;
                v1.y = (c0+1 < len) ? tanhf(a4[3]*TEMP_INV) : 0.f;
                *(float2*)(C + (size_t)r0*ldc + c0) = v0;
                *(float2*)(C + (size_t)r1*ldc + c0) = v1;
            }
        }
    }
}

// ---------------------------------------------------------------------------
// Stage kernels
// ---------------------------------------------------------------------------
__global__ __launch_bounds__(NT, 1)
void tc_proj_qk(const float* __restrict__ q, const float* __restrict__ k,
                const float* __restrict__ w_qs, const float* __restrict__ w_ks,
                float* __restrict__ qp, float* __restrict__ kp)
{
    const int m0 = blockIdx.y * 128, n0 = blockIdx.x * 128;
    if (blockIdx.z == 0)
        tc_body<0>(q, w_qs, DD, DD, nullptr, nullptr, 0, 0, qp, nullptr, DD, 0, m0, n0);
    else
        tc_body<0>(k, w_ks, DD, DD, nullptr, nullptr, 0, 0, kp, nullptr, DD, 0, m0, n0);
}

// Transposed projections: C_b = W (256xK) . X_b^T -> [256,1024] = [d][t]
__global__ __launch_bounds__(NT, 1)
void tc_projT(const float* __restrict__ q, const float* __restrict__ k,
              const float* __restrict__ v,
              const float* __restrict__ w_qs2, const float* __restrict__ w_ks2,
              const float* __restrict__ w_vs,
              float* __restrict__ q2t, float* __restrict__ k2t,
              float* __restrict__ vpt)
{
    const int b = blockIdx.z / 3, w = blockIdx.z % 3;
    const int m0 = blockIdx.y * 128, n0 = blockIdx.x * 128;
    const float* W; const float* X; float* C;
    if      (w == 0) { W = w_qs2; X = q; C = q2t; }
    else if (w == 1) { W = w_ks2; X = k; C = k2t; }
    else             { W = w_vs;  X = v; C = vpt; }
    tc_body<0>(W, X + (size_t)b*LL*DD, DD, DD, nullptr, nullptr, 0, 0,
               C + (size_t)b*DD*LL, nullptr, LL, 0, m0, n0);
}

// q2f = fa @ q2 (as NT with q2t), k2f = fa @ k2. K masked to ceil(len/64)*64.
__global__ __launch_bounds__(NT, 1)
void tc_dual(const float* __restrict__ fa, const float* __restrict__ q2t,
             const float* __restrict__ k2t, const int* __restrict__ lens,
             float* __restrict__ q2f, float* __restrict__ k2f)
{
    const int b = blockIdx.z >> 1, sel = blockIdx.z & 1;
    const int m0 = blockIdx.y * 128, n0 = blockIdx.x * 128;
    const int kmax = ((lens[b] + SLAB - 1) / SLAB) * SLAB;   // fa cols >= len are 0
    const float* A = fa + (size_t)b * LL * LL;
    const float* B = (sel ? k2t : q2t) + (size_t)b * DD * LL;
    float* C = (sel ? k2f : q2f) + (size_t)b * LL * DD;
    tc_body<0>(A, B, kmax, LL, nullptr, nullptr, 0, 0, C, nullptr, DD, 0, m0, n0);
}

__global__ __launch_bounds__(NT, 1)
void tc_logits(const float* __restrict__ qp, const float* __restrict__ kp,
               const float* __restrict__ q2f, const float* __restrict__ k2f,
               const int* __restrict__ lens, float* __restrict__ attn)
{
    const int b = blockIdx.z;
    const size_t od = (size_t)b * LL * DD;
    const int m0 = blockIdx.y * 128, n0 = blockIdx.x * 128;
    const int len = lens[b];
    float* out = attn + (size_t)b * LL * LL;
    if (n0 >= len) {
        // whole n-tile masked: attn = 0, skip GEMM entirely
        const float4 z4 = make_float4(0.f, 0.f, 0.f, 0.f);
        for (int i = threadIdx.x; i < 128 * 32; i += NT) {
            int r = i >> 5, c4 = i & 31;
            *(float4*)(out + (size_t)(m0 + r) * LL + n0 + (c4 << 2)) = z4;
        }
        return;
    }
    tc_body<2>(qp + od, kp + od, DD, DD, q2f + od, k2f + od, DD, DD,
               out, nullptr, LL, len, m0, n0);
}

// out = attn @ vp. attn cols >= len are exactly 0 -> mask K.
__global__ __launch_bounds__(NT, 1)
void tc_av(const float* __restrict__ attn, const float* __restrict__ vpt,
           const int* __restrict__ lens, float* __restrict__ ov)
{
    const int b = blockIdx.z;
    const int m0 = blockIdx.y * 128, n0 = blockIdx.x * 128;
    const int kmax = ((lens[b] + SLAB - 1) / SLAB) * SLAB;
    tc_body<0>(attn + (size_t)b * LL * LL, vpt + (size_t)b * DD * LL, kmax, LL,
               nullptr, nullptr, 0, 0, ov + (size_t)b * LL * DD, nullptr, DD, 0, m0, n0);
}

__global__ __launch_bounds__(NT, 1)
void tc_fc(const float* __restrict__ ov, const float* __restrict__ w_fc,
           const float* __restrict__ q, float* __restrict__ out)
{
    const int m0 = blockIdx.y * 128, n0 = blockIdx.x * 128;
    tc_body<1>(ov, w_fc, DD, DD, nullptr, nullptr, 0, 0, out, q, DD, 0, m0, n0);
}

// ---------------------------------------------------------------------------
// fa kernel (R6 version): one block per (b,i) row, 8192 blocks.
// fa[b,i,j] = softmax_j( mask(j) ? sum_f |x[b,i,f]-x[b,j,f]| * fi[f] : -inf )
// ---------------------------------------------------------------------------
__global__ __launch_bounds__(256)
void fa_kernel(const float* __restrict__ x, const float* __restrict__ fi,
               const int* __restrict__ lens, float* __restrict__ fa)
{
    const int bi = blockIdx.x;
    const int b = bi >> 10, i = bi & 1023;
    const int t = threadIdx.x;

    __shared__ float xi[FF], fis[FF];
    __shared__ float red[256];
    if (t < FF) {
        xi[t]  = x[((size_t)b*LL + i)*FF + t];
        fis[t] = fi[t];
    }
    __syncthreads();
    const int len = lens[b];

    float vals[4];
    #pragma unroll
    for (int r = 0; r < 4; r++) {
        int j = t + r*256;
        const float* xj = x + ((size_t)b*LL + j)*FF;
        float s = 0.f;
        #pragma unroll
        for (int f = 0; f < FF; f++) s += fabsf(xi[f] - xj[f]) * fis[f];
        vals[r] = (j < len) ? s : -INFINITY;
    }
    float m = fmaxf(fmaxf(vals[0], vals[1]), fmaxf(vals[2], vals[3]));
    red[t] = m; __syncthreads();
    for (int s = 128; s > 0; s >>= 1) {
        if (t < s) red[t] = fmaxf(red[t], red[t+s]);
        __syncthreads();
    }
    const float rowmax = red[0];
    __syncthreads();
    float e[4], lsum = 0.f;
    #pragma unroll
    for (int r = 0; r < 4; r++) { e[r] = expf(vals[r] - rowmax); lsum += e[r]; }
    red[t] = lsum; __syncthreads();
    for (int s = 128; s > 0; s >>= 1) {
        if (t < s) red[t] += red[t+s];
        __syncthreads();
    }
    const float inv = 1.0f / red[0];
    float* outp = fa + ((size_t)b*LL + i)*LL;
    #pragma unroll
    for (int r = 0; r < 4; r++) outp[t + r*256] = e[r] * inv;
}

// ---------------------------------------------------------------------------
// LayerNorm
// ---------------------------------------------------------------------------
__global__ __launch_bounds__(256)
void ln_kernel(const float* __restrict__ in, const float* __restrict__ gamma,
               const float* __restrict__ beta, float* __restrict__ out)
{
    const int row = blockIdx.x;
    const int t = threadIdx.x;
    __shared__ float red[256];
    const float v = in[(size_t)row*DD + t];
    red[t] = v; __syncthreads();
    for (int s = 128; s > 0; s >>= 1) {
        if (t < s) red[t] += red[t+s];
        __syncthreads();
    }
    const float mean = red[0] * (1.0f/DD);
    __syncthreads();
    const float d = v - mean;
    red[t] = d * d; __syncthreads();
    for (int s = 128; s > 0; s >>= 1) {
        if (t < s) red[t] += red[t+s];
        __syncthreads();
    }
    const float var = red[0] * (1.0f/DD);
    out[(size_t)row*DD + t] = d * rsqrtf(var + LN_EPS) * gamma[t] + beta[t];
}

// ---------------------------------------------------------------------------
// Host launch
// ---------------------------------------------------------------------------
extern "C" void kernel_launch(void* const* d_in, const int* in_sizes, int n_in,
                              void* d_out, int out_size)
{
    int li = -1;
    for (int i = 0; i < n_in; i++) if (in_sizes[i] == BB) { li = i; break; }

    const float* q = (const float*)d_in[0];
    const float* k = (const float*)d_in[1];
    const float* v = (const float*)d_in[2];
    const float* x = (const float*)d_in[3];
    const int* lens;
    const float *w_qs, *w_ks, *w_vs, *w_qs2, *w_ks2, *w_fc, *fi, *gamma, *beta;
    if (li == 4) {
        lens  = (const int*)d_in[4];
        w_qs  = (const float*)d_in[5];  w_ks  = (const float*)d_in[6];
        w_vs  = (const float*)d_in[7];  w_qs2 = (const float*)d_in[8];
        w_ks2 = (const float*)d_in[9];  w_fc  = (const float*)d_in[10];
        fi    = (const float*)d_in[11]; gamma = (const float*)d_in[12];
        beta  = (const float*)d_in[13];
    } else {
        w_qs  = (const float*)d_in[4];  w_ks  = (const float*)d_in[5];
        w_vs  = (const float*)d_in[6];  w_qs2 = (const float*)d_in[7];
        w_ks2 = (const float*)d_in[8];  w_fc  = (const float*)d_in[9];
        fi    = (const float*)d_in[10]; gamma = (const float*)d_in[11];
        beta  = (const float*)d_in[12]; lens  = (const int*)d_in[13];
    }

    float *qp, *kp, *q2t, *k2t, *vpt, *q2f, *k2f, *ov, *fc, *fa, *attn_scratch;
    cudaGetSymbolAddress((void**)&qp,  g_qp);
    cudaGetSymbolAddress((void**)&kp,  g_kp);
    cudaGetSymbolAddress((void**)&q2t, g_q2t);
    cudaGetSymbolAddress((void**)&k2t, g_k2t);
    cudaGetSymbolAddress((void**)&vpt, g_vpt);
    cudaGetSymbolAddress((void**)&q2f, g_q2f);
    cudaGetSymbolAddress((void**)&k2f, g_k2f);
    cudaGetSymbolAddress((void**)&ov,  g_ov);
    cudaGetSymbolAddress((void**)&fc,  g_fc);
    cudaGetSymbolAddress((void**)&fa,  g_fa);
    cudaGetSymbolAddress((void**)&attn_scratch, g_attn_scratch);

    const size_t OUT_ELEMS  = (size_t)BB*LL*DD;
    const size_t ATTN_ELEMS = (size_t)BB*LL*LL;
    float* attn = ((size_t)out_size >= OUT_ELEMS + ATTN_ELEMS)
                ? (float*)d_out + OUT_ELEMS
                : attn_scratch;

    cudaFuncSetAttribute(tc_proj_qk, cudaFuncAttributeMaxDynamicSharedMemorySize, SMEM_DYN);
    cudaFuncSetAttribute(tc_projT,   cudaFuncAttributeMaxDynamicSharedMemorySize, SMEM_DYN);
    cudaFuncSetAttribute(tc_dual,    cudaFuncAttributeMaxDynamicSharedMemorySize, SMEM_DYN);
    cudaFuncSetAttribute(tc_logits,  cudaFuncAttributeMaxDynamicSharedMemorySize, SMEM_DYN);
    cudaFuncSetAttribute(tc_av,      cudaFuncAttributeMaxDynamicSharedMemorySize, SMEM_DYN);
    cudaFuncSetAttribute(tc_fc,      cudaFuncAttributeMaxDynamicSharedMemorySize, SMEM_DYN);

    const int M = BB * LL;  // 8192
    dim3 blk(NT);
    dim3 blk256(256);

    // qp, kp projections: [8192,256] x [256,256]
    tc_proj_qk<<<dim3(DD/128, M/128, 2), blk, SMEM_DYN>>>(q, k, w_qs, w_ks, qp, kp);

    // transposed projections q2t/k2t/vpt: per batch [256,256] x [1024,256]^T
    tc_projT<<<dim3(LL/128, DD/128, 3*BB), blk, SMEM_DYN>>>(
        q, k, v, w_qs2, w_ks2, w_vs, q2t, k2t, vpt);

    // feature-affinity softmax (R6 version: one block per row)
    fa_kernel<<<M, blk256>>>(x, fi, lens, fa);

    // q2f = fa@q2, k2f = fa@k2 (K masked by len)
    tc_dual<<<dim3(DD/128, LL/128, BB*2), blk, SMEM_DYN>>>(fa, q2t, k2t, lens, q2f, k2f);

    // logits + mask + tanh (fully-masked n-tiles skipped)
    tc_logits<<<dim3(LL/128, LL/128, BB), blk, SMEM_DYN>>>(qp, kp, q2f, k2f, lens, attn);

    // out = attn @ vp (K masked by len)
    tc_av<<<dim3(DD/128, LL/128, BB), blk, SMEM_DYN>>>(attn, vpt, lens, ov);

    // fc + residual, then layernorm
    tc_fc<<<dim3(DD/128, M/128, 1), blk, SMEM_DYN>>>(ov, w_fc, q, fc);
    ln_kernel<<<M, blk256>>>(fc, gamma, beta, (float*)d_out);
}

// round 10
// speedup vs baseline: 2.0436x; 1.2035x over previous
#include <cuda_runtime.h>
#include <cuda_fp16.h>
#include <math.h>
#include <stdint.h>

// Problem constants
#define BB 8
#define LL 1024
#define DD 256
#define FF 11
#define TEMP_INV (1.0f/16.0f)
#define LN_EPS 1e-6f

// GEMM config: 128x128 CTA tile, K-slab 64, 16 warps (4m x 4n), warp tile 32x32
// fp16 2-pass: D = aH*bH + aH*bL  (dropped aL*b ~ 2^-11)
#define SLAB 64
#define TB 16384                // one 128x64 fp16 tile (128 rows x 128B)
#define BUFB (3*TB)             // AH BH BL = 48KB
#define SMEM_DYN (2*BUFB)       // 98304 (double buffered)
#define NT 512                  // threads per CTA

// ---------------------------------------------------------------------------
// Scratch
// ---------------------------------------------------------------------------
__device__ float g_qp [BB*LL*DD];
__device__ float g_kp [BB*LL*DD];
__device__ float g_q2t[BB*LL*DD];   // [b][d][t]
__device__ float g_k2t[BB*LL*DD];
__device__ float g_vpt[BB*LL*DD];
__device__ float g_q2f[BB*LL*DD];
__device__ float g_k2f[BB*LL*DD];
__device__ float g_ov [BB*LL*DD];
__device__ float g_fc [BB*LL*DD];
__device__ float g_fa [(size_t)BB*LL*LL];
__device__ float g_attn_scratch[(size_t)BB*LL*LL];

// ---------------------------------------------------------------------------
// Helpers
// ---------------------------------------------------------------------------
__device__ __forceinline__ uint32_t smem_u32(const void* p) {
    uint32_t a;
    asm("{ .reg .u64 t; cvta.to.shared.u64 t, %1; cvt.u32.u64 %0, t; }"
        : "=r"(a) : "l"(p));
    return a;
}

__device__ __forceinline__ void ldsm_x4(uint32_t* r, uint32_t a) {
    asm volatile("ldmatrix.sync.aligned.m8n8.x4.shared.b16 {%0,%1,%2,%3}, [%4];"
        : "=r"(r[0]), "=r"(r[1]), "=r"(r[2]), "=r"(r[3]) : "r"(a));
}

__device__ __forceinline__ void mma16816(float* c, const uint32_t* a, const uint32_t* b) {
    asm volatile("mma.sync.aligned.m16n8k16.row.col.f32.f16.f16.f32 "
        "{%0,%1,%2,%3}, {%4,%5,%6,%7}, {%8,%9}, {%0,%1,%2,%3};"
        : "+f"(c[0]), "+f"(c[1]), "+f"(c[2]), "+f"(c[3])
        : "r"(a[0]), "r"(a[1]), "r"(a[2]), "r"(a[3]), "r"(b[0]), "r"(b[1]));
}

__device__ __forceinline__ uint32_t pack_h2(float x, float y) {
    __half2 h = __floats2half2_rn(x, y);
    return *(uint32_t*)&h;
}

// Load a 128x64 fp32 tile into registers (4 float4 per thread, 512 threads).
__device__ __forceinline__
void ld_tile(const float* __restrict__ src, int r0, int ld, int k0,
             float4* v, int tid)
{
    #pragma unroll
    for (int i = 0; i < 4; i++) {
        int f = tid + (i << 9);
        int row = f >> 4, c4 = f & 15;
        v[i] = *(const float4*)(src + (size_t)(r0 + row) * ld + k0 + (c4 << 2));
    }
}

// A tile: fp16 hi only, SW128-swizzled.
__device__ __forceinline__
void st_tile_a(const float4* v, char* smem, uint32_t off, int tid)
{
    #pragma unroll
    for (int i = 0; i < 4; i++) {
        int f = tid + (i << 9);
        int row = f >> 4, c4 = f & 15;
        float4 a = v[i];
        uint32_t byte = (row << 7) + (c4 << 3);
        uint32_t sw = byte ^ ((byte >> 3) & 0x70);
        *(uint2*)(smem + off + sw) = make_uint2(pack_h2(a.x, a.y), pack_h2(a.z, a.w));
    }
}

// B tile: fp16 hi + lo (residual), SW128-swizzled.
__device__ __forceinline__
void st_tile_b(const float4* v, char* smem, uint32_t hiOff, uint32_t loOff, int tid)
{
    #pragma unroll
    for (int i = 0; i < 4; i++) {
        int f = tid + (i << 9);
        int row = f >> 4, c4 = f & 15;
        float4 a = v[i];
        __half2 h01 = __floats2half2_rn(a.x, a.y);
        __half2 h23 = __floats2half2_rn(a.z, a.w);
        float rx = a.x - __low2float(h01);
        float ry = a.y - __high2float(h01);
        float rz = a.z - __low2float(h23);
        float rw = a.w - __high2float(h23);
        uint32_t byte = (row << 7) + (c4 << 3);
        uint32_t sw = byte ^ ((byte >> 3) & 0x70);
        *(uint2*)(smem + hiOff + sw) = make_uint2(*(uint32_t*)&h01, *(uint32_t*)&h23);
        *(uint2*)(smem + loOff + sw) = make_uint2(pack_h2(rx, ry), pack_h2(rz, rw));
    }
}

// ---------------------------------------------------------------------------
// fp16x2 mma.sync GEMM body. NT: C[m,n] = sum_k A[m,k]*B[n,k] over
// (A1,B1,kext1,ld1) then (A2,B2,kext2,ld2). kext may be < ld (masked K).
// MODE: 0 plain, 1 +add residual, 2 tanh(acc/16) w/ col mask
// ---------------------------------------------------------------------------
template<int MODE>
__device__ __forceinline__
void tc_body(const float* __restrict__ A1, const float* __restrict__ B1,
             int k1, int ld1,
             const float* __restrict__ A2, const float* __restrict__ B2,
             int k2, int ld2,
             float* __restrict__ C, const float* __restrict__ add,
             int ldc, int len, int m0, int n0)
{
    extern __shared__ char smem[];
    const uint32_t sb = smem_u32(smem);
    const int tid = threadIdx.x;
    const int lane = tid & 31, wid = tid >> 5;
    const int wm = wid & 3, wn = wid >> 2;

    float acc[2][4][4] = {};

    // ldmatrix lane addressing (128B rows, SW128-style XOR)
    const int a_row = wm * 32 + (lane & 15);
    const uint32_t a_colp = (lane >> 4) << 4;
    const uint32_t a_xor = (uint32_t)(a_row & 7) << 4;
    const int b_row = wn * 32 + ((lane >> 4) << 3) + (lane & 7);
    const uint32_t b_colp = ((lane >> 3) & 1) << 4;
    const uint32_t b_xor = (uint32_t)(b_row & 7) << 4;

    const int n1 = k1 / SLAB;
    const int nslabs = n1 + (A2 ? k2 / SLAB : 0);

    float4 av[4], bv[4];
    // prologue: slab 0
    ld_tile(A1, m0, ld1, 0, av, tid);
    ld_tile(B1, n0, ld1, 0, bv, tid);
    st_tile_a(av, smem, 0, tid);
    st_tile_b(bv, smem, TB, 2*TB, tid);
    __syncthreads();

    for (int s = 0; s < nslabs; s++) {
        const uint32_t bo = (s & 1) * BUFB;
        const uint32_t bn = bo ^ BUFB;
        const bool has = (s + 1) < nslabs;
        const float *An = A1, *Bn = B1; int ldn = ld1, k0n = 0;
        if (has) {
            int sn = s + 1;
            if (sn < n1) { An = A1; Bn = B1; ldn = ld1; k0n = sn * SLAB; }
            else         { An = A2; Bn = B2; ldn = ld2; k0n = (sn - n1) * SLAB; }
        }

        #pragma unroll
        for (int kk = 0; kk < 4; kk++) {
            if (kk == 0 && has) ld_tile(An, m0, ldn, k0n, av, tid);
            if (kk == 2 && has) {
                st_tile_a(av, smem, bn, tid);
                ld_tile(Bn, n0, ldn, k0n, bv, tid);
            }
            if (kk == 3 && has) st_tile_b(bv, smem, bn + TB, bn + 2*TB, tid);

            const uint32_t kb = kk << 5;
            uint32_t bH[8], bL[8];
            {
                uint32_t r = (uint32_t)b_row << 7;
                uint32_t c = (kb + b_colp) ^ b_xor;
                ldsm_x4(bH + 0, sb + bo + TB + r + c);
                ldsm_x4(bH + 4, sb + bo + TB + r + 2048 + c);
                ldsm_x4(bL + 0, sb + bo + 2*TB + r + c);
                ldsm_x4(bL + 4, sb + bo + 2*TB + r + 2048 + c);
            }
            #pragma unroll
            for (int mt = 0; mt < 2; mt++) {
                uint32_t aH[4];
                uint32_t r = (uint32_t)(a_row + mt*16) << 7;
                uint32_t c = (kb + a_colp) ^ a_xor;
                ldsm_x4(aH, sb + bo + r + c);
                #pragma unroll
                for (int nt = 0; nt < 4; nt++) {
                    mma16816(acc[mt][nt], aH, bH + nt*2);
                    mma16816(acc[mt][nt], aH, bL + nt*2);
                }
            }
        }
        if (has) __syncthreads();
    }

    // epilogue
    const int mg = m0 + wm * 32;
    const int ng = n0 + wn * 32;
    const int rq = lane >> 2;
    const int cq = (lane & 3) << 1;
    #pragma unroll
    for (int mt = 0; mt < 2; mt++) {
        #pragma unroll
        for (int nt = 0; nt < 4; nt++) {
            const float* a4 = acc[mt][nt];
            const int r0 = mg + mt*16 + rq, r1 = r0 + 8;
            const int c0 = ng + nt*8 + cq;
            if (MODE == 0) {
                *(float2*)(C + (size_t)r0*ldc + c0) = make_float2(a4[0], a4[1]);
                *(float2*)(C + (size_t)r1*ldc + c0) = make_float2(a4[2], a4[3]);
            } else if (MODE == 1) {
                float2 x0 = *(const float2*)(add + (size_t)r0*ldc + c0);
                float2 x1 = *(const float2*)(add + (size_t)r1*ldc + c0);
                *(float2*)(C + (size_t)r0*ldc + c0) = make_float2(a4[0]+x0.x, a4[1]+x0.y);
                *(float2*)(C + (size_t)r1*ldc + c0) = make_float2(a4[2]+x1.x, a4[3]+x1.y);
            } else {
                float2 v0, v1;
                v0.x = (c0   < len) ? tanhf(a4[0]*TEMP_INV) : 0.f;
                v0.y = (c0+1 < len) ? tanhf(a4[1]*TEMP_INV) : 0.f;
                v1.x = (c0   < len) ? tanhf(a4[2]*TEMP_INV) : 0.f;
                v1.y = (c0+1 < len) ? tanhf(a4[3]*TEMP_INV) : 0.f;
                *(float2*)(C + (size_t)r0*ldc + c0) = v0;
                *(float2*)(C + (size_t)r1*ldc + c0) = v1;
            }
        }
    }
}

// ---------------------------------------------------------------------------
// Stage kernels
// ---------------------------------------------------------------------------
__global__ __launch_bounds__(NT, 1)
void tc_proj_qk(const float* __restrict__ q, const float* __restrict__ k,
                const float* __restrict__ w_qs, const float* __restrict__ w_ks,
                float* __restrict__ qp, float* __restrict__ kp)
{
    const int m0 = blockIdx.y * 128, n0 = blockIdx.x * 128;
    if (blockIdx.z == 0)
        tc_body<0>(q, w_qs, DD, DD, nullptr, nullptr, 0, 0, qp, nullptr, DD, 0, m0, n0);
    else
        tc_body<0>(k, w_ks, DD, DD, nullptr, nullptr, 0, 0, kp, nullptr, DD, 0, m0, n0);
}

// Transposed projections: C_b = W (256xK) . X_b^T -> [256,1024] = [d][t]
__global__ __launch_bounds__(NT, 1)
void tc_projT(const float* __restrict__ q, const float* __restrict__ k,
              const float* __restrict__ v,
              const float* __restrict__ w_qs2, const float* __restrict__ w_ks2,
              const float* __restrict__ w_vs,
              float* __restrict__ q2t, float* __restrict__ k2t,
              float* __restrict__ vpt)
{
    const int b = blockIdx.z / 3, w = blockIdx.z % 3;
    const int m0 = blockIdx.y * 128, n0 = blockIdx.x * 128;
    const float* W; const float* X; float* C;
    if      (w == 0) { W = w_qs2; X = q; C = q2t; }
    else if (w == 1) { W = w_ks2; X = k; C = k2t; }
    else             { W = w_vs;  X = v; C = vpt; }
    tc_body<0>(W, X + (size_t)b*LL*DD, DD, DD, nullptr, nullptr, 0, 0,
               C + (size_t)b*DD*LL, nullptr, LL, 0, m0, n0);
}

// q2f = fa @ q2 (as NT with q2t), k2f = fa @ k2. K masked to ceil(len/64)*64.
__global__ __launch_bounds__(NT, 1)
void tc_dual(const float* __restrict__ fa, const float* __restrict__ q2t,
             const float* __restrict__ k2t, const int* __restrict__ lens,
             float* __restrict__ q2f, float* __restrict__ k2f)
{
    const int b = blockIdx.z >> 1, sel = blockIdx.z & 1;
    const int m0 = blockIdx.y * 128, n0 = blockIdx.x * 128;
    const int kmax = ((lens[b] + SLAB - 1) / SLAB) * SLAB;   // fa cols >= len are 0
    const float* A = fa + (size_t)b * LL * LL;
    const float* B = (sel ? k2t : q2t) + (size_t)b * DD * LL;
    float* C = (sel ? k2f : q2f) + (size_t)b * LL * DD;
    tc_body<0>(A, B, kmax, LL, nullptr, nullptr, 0, 0, C, nullptr, DD, 0, m0, n0);
}

__global__ __launch_bounds__(NT, 1)
void tc_logits(const float* __restrict__ qp, const float* __restrict__ kp,
               const float* __restrict__ q2f, const float* __restrict__ k2f,
               const int* __restrict__ lens, float* __restrict__ attn)
{
    const int b = blockIdx.z;
    const size_t od = (size_t)b * LL * DD;
    const int m0 = blockIdx.y * 128, n0 = blockIdx.x * 128;
    const int len = lens[b];
    float* out = attn + (size_t)b * LL * LL;
    if (n0 >= len) {
        // whole n-tile masked: attn = 0, skip GEMM entirely
        const float4 z4 = make_float4(0.f, 0.f, 0.f, 0.f);
        for (int i = threadIdx.x; i < 128 * 32; i += NT) {
            int r = i >> 5, c4 = i & 31;
            *(float4*)(out + (size_t)(m0 + r) * LL + n0 + (c4 << 2)) = z4;
        }
        return;
    }
    tc_body<2>(qp + od, kp + od, DD, DD, q2f + od, k2f + od, DD, DD,
               out, nullptr, LL, len, m0, n0);
}

// out = attn @ vp. attn cols >= len are exactly 0 -> mask K.
__global__ __launch_bounds__(NT, 1)
void tc_av(const float* __restrict__ attn, const float* __restrict__ vpt,
           const int* __restrict__ lens, float* __restrict__ ov)
{
    const int b = blockIdx.z;
    const int m0 = blockIdx.y * 128, n0 = blockIdx.x * 128;
    const int kmax = ((lens[b] + SLAB - 1) / SLAB) * SLAB;
    tc_body<0>(attn + (size_t)b * LL * LL, vpt + (size_t)b * DD * LL, kmax, LL,
               nullptr, nullptr, 0, 0, ov + (size_t)b * LL * DD, nullptr, DD, 0, m0, n0);
}

__global__ __launch_bounds__(NT, 1)
void tc_fc(const float* __restrict__ ov, const float* __restrict__ w_fc,
           const float* __restrict__ q, float* __restrict__ out)
{
    const int m0 = blockIdx.y * 128, n0 = blockIdx.x * 128;
    tc_body<1>(ov, w_fc, DD, DD, nullptr, nullptr, 0, 0, out, q, DD, 0, m0, n0);
}

// ---------------------------------------------------------------------------
// fa kernel: one block per (b,i) row, 8192 blocks.
// fa[b,i,j] = softmax_j( mask(j) ? sum_f |x[b,i,f]-x[b,j,f]| * fi[f] : -inf )
// ---------------------------------------------------------------------------
__global__ __launch_bounds__(256)
void fa_kernel(const float* __restrict__ x, const float* __restrict__ fi,
               const int* __restrict__ lens, float* __restrict__ fa)
{
    const int bi = blockIdx.x;
    const int b = bi >> 10, i = bi & 1023;
    const int t = threadIdx.x;

    __shared__ float xi[FF], fis[FF];
    __shared__ float red[256];
    if (t < FF) {
        xi[t]  = x[((size_t)b*LL + i)*FF + t];
        fis[t] = fi[t];
    }
    __syncthreads();
    const int len = lens[b];

    float vals[4];
    #pragma unroll
    for (int r = 0; r < 4; r++) {
        int j = t + r*256;
        const float* xj = x + ((size_t)b*LL + j)*FF;
        float s = 0.f;
        #pragma unroll
        for (int f = 0; f < FF; f++) s += fabsf(xi[f] - xj[f]) * fis[f];
        vals[r] = (j < len) ? s : -INFINITY;
    }
    float m = fmaxf(fmaxf(vals[0], vals[1]), fmaxf(vals[2], vals[3]));
    red[t] = m; __syncthreads();
    for (int s = 128; s > 0; s >>= 1) {
        if (t < s) red[t] = fmaxf(red[t], red[t+s]);
        __syncthreads();
    }
    const float rowmax = red[0];
    __syncthreads();
    float e[4], lsum = 0.f;
    #pragma unroll
    for (int r = 0; r < 4; r++) { e[r] = expf(vals[r] - rowmax); lsum += e[r]; }
    red[t] = lsum; __syncthreads();
    for (int s = 128; s > 0; s >>= 1) {
        if (t < s) red[t] += red[t+s];
        __syncthreads();
    }
    const float inv = 1.0f / red[0];
    float* outp = fa + ((size_t)b*LL + i)*LL;
    #pragma unroll
    for (int r = 0; r < 4; r++) outp[t + r*256] = e[r] * inv;
}

// ---------------------------------------------------------------------------
// LayerNorm
// ---------------------------------------------------------------------------
__global__ __launch_bounds__(256)
void ln_kernel(const float* __restrict__ in, const float* __restrict__ gamma,
               const float* __restrict__ beta, float* __restrict__ out)
{
    const int row = blockIdx.x;
    const int t = threadIdx.x;
    __shared__ float red[256];
    const float v = in[(size_t)row*DD + t];
    red[t] = v; __syncthreads();
    for (int s = 128; s > 0; s >>= 1) {
        if (t < s) red[t] += red[t+s];
        __syncthreads();
    }
    const float mean = red[0] * (1.0f/DD);
    __syncthreads();
    const float d = v - mean;
    red[t] = d * d; __syncthreads();
    for (int s = 128; s > 0; s >>= 1) {
        if (t < s) red[t] += red[t+s];
        __syncthreads();
    }
    const float var = red[0] * (1.0f/DD);
    out[(size_t)row*DD + t] = d * rsqrtf(var + LN_EPS) * gamma[t] + beta[t];
}

// ---------------------------------------------------------------------------
// Host launch
// ---------------------------------------------------------------------------
extern "C" void kernel_launch(void* const* d_in, const int* in_sizes, int n_in,
                              void* d_out, int out_size)
{
    int li = -1;
    for (int i = 0; i < n_in; i++) if (in_sizes[i] == BB) { li = i; break; }

    const float* q = (const float*)d_in[0];
    const float* k = (const float*)d_in[1];
    const float* v = (const float*)d_in[2];
    const float* x = (const float*)d_in[3];
    const int* lens;
    const float *w_qs, *w_ks, *w_vs, *w_qs2, *w_ks2, *w_fc, *fi, *gamma, *beta;
    if (li == 4) {
        lens  = (const int*)d_in[4];
        w_qs  = (const float*)d_in[5];  w_ks  = (const float*)d_in[6];
        w_vs  = (const float*)d_in[7];  w_qs2 = (const float*)d_in[8];
        w_ks2 = (const float*)d_in[9];  w_fc  = (const float*)d_in[10];
        fi    = (const float*)d_in[11]; gamma = (const float*)d_in[12];
        beta  = (const float*)d_in[13];
    } else {
        w_qs  = (const float*)d_in[4];  w_ks  = (const float*)d_in[5];
        w_vs  = (const float*)d_in[6];  w_qs2 = (const float*)d_in[7];
        w_ks2 = (const float*)d_in[8];  w_fc  = (const float*)d_in[9];
        fi    = (const float*)d_in[10]; gamma = (const float*)d_in[11];
        beta  = (const float*)d_in[12]; lens  = (const int*)d_in[13];
    }

    float *qp, *kp, *q2t, *k2t, *vpt, *q2f, *k2f, *ov, *fc, *fa, *attn_scratch;
    cudaGetSymbolAddress((void**)&qp,  g_qp);
    cudaGetSymbolAddress((void**)&kp,  g_kp);
    cudaGetSymbolAddress((void**)&q2t, g_q2t);
    cudaGetSymbolAddress((void**)&k2t, g_k2t);
    cudaGetSymbolAddress((void**)&vpt, g_vpt);
    cudaGetSymbolAddress((void**)&q2f, g_q2f);
    cudaGetSymbolAddress((void**)&k2f, g_k2f);
    cudaGetSymbolAddress((void**)&ov,  g_ov);
    cudaGetSymbolAddress((void**)&fc,  g_fc);
    cudaGetSymbolAddress((void**)&fa,  g_fa);
    cudaGetSymbolAddress((void**)&attn_scratch, g_attn_scratch);

    const size_t OUT_ELEMS  = (size_t)BB*LL*DD;
    const size_t ATTN_ELEMS = (size_t)BB*LL*LL;
    float* attn = ((size_t)out_size >= OUT_ELEMS + ATTN_ELEMS)
                ? (float*)d_out + OUT_ELEMS
                : attn_scratch;

    cudaFuncSetAttribute(tc_proj_qk, cudaFuncAttributeMaxDynamicSharedMemorySize, SMEM_DYN);
    cudaFuncSetAttribute(tc_projT,   cudaFuncAttributeMaxDynamicSharedMemorySize, SMEM_DYN);
    cudaFuncSetAttribute(tc_dual,    cudaFuncAttributeMaxDynamicSharedMemorySize, SMEM_DYN);
    cudaFuncSetAttribute(tc_logits,  cudaFuncAttributeMaxDynamicSharedMemorySize, SMEM_DYN);
    cudaFuncSetAttribute(tc_av,      cudaFuncAttributeMaxDynamicSharedMemorySize, SMEM_DYN);
    cudaFuncSetAttribute(tc_fc,      cudaFuncAttributeMaxDynamicSharedMemorySize, SMEM_DYN);

    const int M = BB * LL;  // 8192
    dim3 blk(NT);
    dim3 blk256(256);

    // qp, kp projections: [8192,256] x [256,256]
    tc_proj_qk<<<dim3(DD/128, M/128, 2), blk, SMEM_DYN>>>(q, k, w_qs, w_ks, qp, kp);

    // transposed projections q2t/k2t/vpt: per batch [256,256] x [1024,256]^T
    tc_projT<<<dim3(LL/128, DD/128, 3*BB), blk, SMEM_DYN>>>(
        q, k, v, w_qs2, w_ks2, w_vs, q2t, k2t, vpt);

    // feature-affinity softmax (one block per row)
    fa_kernel<<<M, blk256>>>(x, fi, lens, fa);

    // q2f = fa@q2, k2f = fa@k2 (K masked by len)
    tc_dual<<<dim3(DD/128, LL/128, BB*2), blk, SMEM_DYN>>>(fa, q2t, k2t, lens, q2f, k2f);

    // logits + mask + tanh (fully-masked n-tiles skipped)
    tc_logits<<<dim3(LL/128, LL/128, BB), blk, SMEM_DYN>>>(qp, kp, q2f, k2f, lens, attn);

    // out = attn @ vp (K masked by len)
    tc_av<<<dim3(DD/128, LL/128, BB), blk, SMEM_DYN>>>(attn, vpt, lens, ov);

    // fc + residual, then layernorm
    tc_fc<<<dim3(DD/128, M/128, 1), blk, SMEM_DYN>>>(ov, w_fc, q, fc);
    ln_kernel<<<M, blk256>>>(fc, gamma, beta, (float*)d_out);
}

// round 11
// speedup vs baseline: 2.2280x; 1.0903x over previous
#include <cuda_runtime.h>
#include <cuda_fp16.h>
#include <math.h>
#include <stdint.h>

// Problem constants
#define BB 8
#define LL 1024
#define DD 256
#define FF 11
#define TEMP_INV (1.0f/16.0f)
#define LN_EPS 1e-6f

// GEMM config: 128x128 CTA tile, K-slab 64, 16 warps (4m x 4n), warp tile 32x32
// fp16 2-pass: D = aH*bH + aH*bL  (dropped aL*b ~ 2^-11)
#define SLAB 64
#define TB 16384                // one 128x64 fp16 tile (128 rows x 128B)
#define BUFB (3*TB)             // AH BH BL = 48KB
#define SMEM_DYN (2*BUFB)       // 98304 (double buffered)
#define NT 512                  // threads per CTA

// ---------------------------------------------------------------------------
// Scratch
// ---------------------------------------------------------------------------
__device__ float g_qp [BB*LL*DD];
__device__ float g_kp [BB*LL*DD];
__device__ float g_q2t[BB*LL*DD];   // [b][d][t]
__device__ float g_k2t[BB*LL*DD];
__device__ float g_vpt[BB*LL*DD];
__device__ float g_q2f[BB*LL*DD];
__device__ float g_k2f[BB*LL*DD];
__device__ float g_ov [BB*LL*DD];
__device__ float g_fc [BB*LL*DD];
__device__ float g_fa [(size_t)BB*LL*LL];
__device__ float g_attn_scratch[(size_t)BB*LL*LL];

// ---------------------------------------------------------------------------
// Helpers
// ---------------------------------------------------------------------------
__device__ __forceinline__ uint32_t smem_u32(const void* p) {
    uint32_t a;
    asm("{ .reg .u64 t; cvta.to.shared.u64 t, %1; cvt.u32.u64 %0, t; }"
        : "=r"(a) : "l"(p));
    return a;
}

__device__ __forceinline__ void ldsm_x4(uint32_t* r, uint32_t a) {
    asm volatile("ldmatrix.sync.aligned.m8n8.x4.shared.b16 {%0,%1,%2,%3}, [%4];"
        : "=r"(r[0]), "=r"(r[1]), "=r"(r[2]), "=r"(r[3]) : "r"(a));
}

__device__ __forceinline__ void mma16816(float* c, const uint32_t* a, const uint32_t* b) {
    asm volatile("mma.sync.aligned.m16n8k16.row.col.f32.f16.f16.f32 "
        "{%0,%1,%2,%3}, {%4,%5,%6,%7}, {%8,%9}, {%0,%1,%2,%3};"
        : "+f"(c[0]), "+f"(c[1]), "+f"(c[2]), "+f"(c[3])
        : "r"(a[0]), "r"(a[1]), "r"(a[2]), "r"(a[3]), "r"(b[0]), "r"(b[1]));
}

__device__ __forceinline__ uint32_t pack_h2(float x, float y) {
    __half2 h = __floats2half2_rn(x, y);
    return *(uint32_t*)&h;
}

// Load a 128x64 fp32 tile into registers (4 float4 per thread, 512 threads).
__device__ __forceinline__
void ld_tile(const float* __restrict__ src, int r0, int ld, int k0,
             float4* v, int tid)
{
    #pragma unroll
    for (int i = 0; i < 4; i++) {
        int f = tid + (i << 9);
        int row = f >> 4, c4 = f & 15;
        v[i] = *(const float4*)(src + (size_t)(r0 + row) * ld + k0 + (c4 << 2));
    }
}

// A tile: fp16 hi only, SW128-swizzled.
__device__ __forceinline__
void st_tile_a(const float4* v, char* smem, uint32_t off, int tid)
{
    #pragma unroll
    for (int i = 0; i < 4; i++) {
        int f = tid + (i << 9);
        int row = f >> 4, c4 = f & 15;
        float4 a = v[i];
        uint32_t byte = (row << 7) + (c4 << 3);
        uint32_t sw = byte ^ ((byte >> 3) & 0x70);
        *(uint2*)(smem + off + sw) = make_uint2(pack_h2(a.x, a.y), pack_h2(a.z, a.w));
    }
}

// B tile: fp16 hi + lo (residual), SW128-swizzled.
__device__ __forceinline__
void st_tile_b(const float4* v, char* smem, uint32_t hiOff, uint32_t loOff, int tid)
{
    #pragma unroll
    for (int i = 0; i < 4; i++) {
        int f = tid + (i << 9);
        int row = f >> 4, c4 = f & 15;
        float4 a = v[i];
        __half2 h01 = __floats2half2_rn(a.x, a.y);
        __half2 h23 = __floats2half2_rn(a.z, a.w);
        float rx = a.x - __low2float(h01);
        float ry = a.y - __high2float(h01);
        float rz = a.z - __low2float(h23);
        float rw = a.w - __high2float(h23);
        uint32_t byte = (row << 7) + (c4 << 3);
        uint32_t sw = byte ^ ((byte >> 3) & 0x70);
        *(uint2*)(smem + hiOff + sw) = make_uint2(*(uint32_t*)&h01, *(uint32_t*)&h23);
        *(uint2*)(smem + loOff + sw) = make_uint2(pack_h2(rx, ry), pack_h2(rz, rw));
    }
}

// ---------------------------------------------------------------------------
// fp16x2 mma.sync GEMM body. NT: C[m,n] = sum_k A[m,k]*B[n,k] over
// (A1,B1,kext1,ld1) then (A2,B2,kext2,ld2). kext may be < ld (masked K).
// MODE: 0 plain, 1 +add residual, 2 tanh(acc/16) w/ col mask
// ---------------------------------------------------------------------------
template<int MODE>
__device__ __forceinline__
void tc_body(const float* __restrict__ A1, const float* __restrict__ B1,
             int k1, int ld1,
             const float* __restrict__ A2, const float* __restrict__ B2,
             int k2, int ld2,
             float* __restrict__ C, const float* __restrict__ add,
             int ldc, int len, int m0, int n0)
{
    extern __shared__ char smem[];
    const uint32_t sb = smem_u32(smem);
    const int tid = threadIdx.x;
    const int lane = tid & 31, wid = tid >> 5;
    const int wm = wid & 3, wn = wid >> 2;

    float acc[2][4][4] = {};

    // ldmatrix lane addressing (128B rows, SW128-style XOR)
    const int a_row = wm * 32 + (lane & 15);
    const uint32_t a_colp = (lane >> 4) << 4;
    const uint32_t a_xor = (uint32_t)(a_row & 7) << 4;
    const int b_row = wn * 32 + ((lane >> 4) << 3) + (lane & 7);
    const uint32_t b_colp = ((lane >> 3) & 1) << 4;
    const uint32_t b_xor = (uint32_t)(b_row & 7) << 4;

    const int n1 = k1 / SLAB;
    const int nslabs = n1 + (A2 ? k2 / SLAB : 0);

    float4 av[4], bv[4];
    // prologue: slab 0
    ld_tile(A1, m0, ld1, 0, av, tid);
    ld_tile(B1, n0, ld1, 0, bv, tid);
    st_tile_a(av, smem, 0, tid);
    st_tile_b(bv, smem, TB, 2*TB, tid);
    __syncthreads();

    for (int s = 0; s < nslabs; s++) {
        const uint32_t bo = (s & 1) * BUFB;
        const uint32_t bn = bo ^ BUFB;
        const bool has = (s + 1) < nslabs;
        const float *An = A1, *Bn = B1; int ldn = ld1, k0n = 0;
        if (has) {
            int sn = s + 1;
            if (sn < n1) { An = A1; Bn = B1; ldn = ld1; k0n = sn * SLAB; }
            else         { An = A2; Bn = B2; ldn = ld2; k0n = (sn - n1) * SLAB; }
        }

        #pragma unroll
        for (int kk = 0; kk < 4; kk++) {
            if (kk == 0 && has) ld_tile(An, m0, ldn, k0n, av, tid);
            if (kk == 2 && has) {
                st_tile_a(av, smem, bn, tid);
                ld_tile(Bn, n0, ldn, k0n, bv, tid);
            }
            if (kk == 3 && has) st_tile_b(bv, smem, bn + TB, bn + 2*TB, tid);

            const uint32_t kb = kk << 5;
            uint32_t bH[8], bL[8];
            {
                uint32_t r = (uint32_t)b_row << 7;
                uint32_t c = (kb + b_colp) ^ b_xor;
                ldsm_x4(bH + 0, sb + bo + TB + r + c);
                ldsm_x4(bH + 4, sb + bo + TB + r + 2048 + c);
                ldsm_x4(bL + 0, sb + bo + 2*TB + r + c);
                ldsm_x4(bL + 4, sb + bo + 2*TB + r + 2048 + c);
            }
            #pragma unroll
            for (int mt = 0; mt < 2; mt++) {
                uint32_t aH[4];
                uint32_t r = (uint32_t)(a_row + mt*16) << 7;
                uint32_t c = (kb + a_colp) ^ a_xor;
                ldsm_x4(aH, sb + bo + r + c);
                #pragma unroll
                for (int nt = 0; nt < 4; nt++) {
                    mma16816(acc[mt][nt], aH, bH + nt*2);
                    mma16816(acc[mt][nt], aH, bL + nt*2);
                }
            }
        }
        if (has) __syncthreads();
    }

    // epilogue
    const int mg = m0 + wm * 32;
    const int ng = n0 + wn * 32;
    const int rq = lane >> 2;
    const int cq = (lane & 3) << 1;
    #pragma unroll
    for (int mt = 0; mt < 2; mt++) {
        #pragma unroll
        for (int nt = 0; nt < 4; nt++) {
            const float* a4 = acc[mt][nt];
            const int r0 = mg + mt*16 + rq, r1 = r0 + 8;
            const int c0 = ng + nt*8 + cq;
            if (MODE == 0) {
                *(float2*)(C + (size_t)r0*ldc + c0) = make_float2(a4[0], a4[1]);
                *(float2*)(C + (size_t)r1*ldc + c0) = make_float2(a4[2], a4[3]);
            } else if (MODE == 1) {
                float2 x0 = *(const float2*)(add + (size_t)r0*ldc + c0);
                float2 x1 = *(const float2*)(add + (size_t)r1*ldc + c0);
                *(float2*)(C + (size_t)r0*ldc + c0) = make_float2(a4[0]+x0.x, a4[1]+x0.y);
                *(float2*)(C + (size_t)r1*ldc + c0) = make_float2(a4[2]+x1.x, a4[3]+x1.y);
            } else {
                float2 v0, v1;
                v0.x = (c0   < len) ? tanhf(a4[0]*TEMP_INV) : 0.f;
                v0.y = (c0+1 < len) ? tanhf(a4[1]*TEMP_INV) : 0.f;
                v1.x = (c0   < len) ? tanhf(a4[2]*TEMP_INV) : 0.f;
                v1.y = (c0+1 < len) ? tanhf(a4[3]*TEMP_INV) : 0.f;
                *(float2*)(C + (size_t)r0*ldc + c0) = v0;
                *(float2*)(C + (size_t)r1*ldc + c0) = v1;
            }
        }
    }
}

// ---------------------------------------------------------------------------
// Stage kernels
// ---------------------------------------------------------------------------
__global__ __launch_bounds__(NT, 1)
void tc_proj_qk(const float* __restrict__ q, const float* __restrict__ k,
                const float* __restrict__ w_qs, const float* __restrict__ w_ks,
                float* __restrict__ qp, float* __restrict__ kp)
{
    const int m0 = blockIdx.y * 128, n0 = blockIdx.x * 128;
    if (blockIdx.z == 0)
        tc_body<0>(q, w_qs, DD, DD, nullptr, nullptr, 0, 0, qp, nullptr, DD, 0, m0, n0);
    else
        tc_body<0>(k, w_ks, DD, DD, nullptr, nullptr, 0, 0, kp, nullptr, DD, 0, m0, n0);
}

// Transposed projections: C_b = W (256xK) . X_b^T -> [256,1024] = [d][t]
__global__ __launch_bounds__(NT, 1)
void tc_projT(const float* __restrict__ q, const float* __restrict__ k,
              const float* __restrict__ v,
              const float* __restrict__ w_qs2, const float* __restrict__ w_ks2,
              const float* __restrict__ w_vs,
              float* __restrict__ q2t, float* __restrict__ k2t,
              float* __restrict__ vpt)
{
    const int b = blockIdx.z / 3, w = blockIdx.z % 3;
    const int m0 = blockIdx.y * 128, n0 = blockIdx.x * 128;
    const float* W; const float* X; float* C;
    if      (w == 0) { W = w_qs2; X = q; C = q2t; }
    else if (w == 1) { W = w_ks2; X = k; C = k2t; }
    else             { W = w_vs;  X = v; C = vpt; }
    tc_body<0>(W, X + (size_t)b*LL*DD, DD, DD, nullptr, nullptr, 0, 0,
               C + (size_t)b*DD*LL, nullptr, LL, 0, m0, n0);
}

// q2f = fa @ q2 (as NT with q2t), k2f = fa @ k2. K masked to ceil(len/64)*64.
__global__ __launch_bounds__(NT, 1)
void tc_dual(const float* __restrict__ fa, const float* __restrict__ q2t,
             const float* __restrict__ k2t, const int* __restrict__ lens,
             float* __restrict__ q2f, float* __restrict__ k2f)
{
    const int b = blockIdx.z >> 1, sel = blockIdx.z & 1;
    const int m0 = blockIdx.y * 128, n0 = blockIdx.x * 128;
    const int kmax = ((lens[b] + SLAB - 1) / SLAB) * SLAB;   // fa cols >= len are 0
    const float* A = fa + (size_t)b * LL * LL;
    const float* B = (sel ? k2t : q2t) + (size_t)b * DD * LL;
    float* C = (sel ? k2f : q2f) + (size_t)b * LL * DD;
    tc_body<0>(A, B, kmax, LL, nullptr, nullptr, 0, 0, C, nullptr, DD, 0, m0, n0);
}

__global__ __launch_bounds__(NT, 1)
void tc_logits(const float* __restrict__ qp, const float* __restrict__ kp,
               const float* __restrict__ q2f, const float* __restrict__ k2f,
               const int* __restrict__ lens, float* __restrict__ attn)
{
    const int b = blockIdx.z;
    const size_t od = (size_t)b * LL * DD;
    const int m0 = blockIdx.y * 128, n0 = blockIdx.x * 128;
    const int len = lens[b];
    float* out = attn + (size_t)b * LL * LL;
    if (n0 >= len) {
        // whole n-tile masked: attn = 0, skip GEMM entirely
        const float4 z4 = make_float4(0.f, 0.f, 0.f, 0.f);
        for (int i = threadIdx.x; i < 128 * 32; i += NT) {
            int r = i >> 5, c4 = i & 31;
            *(float4*)(out + (size_t)(m0 + r) * LL + n0 + (c4 << 2)) = z4;
        }
        return;
    }
    tc_body<2>(qp + od, kp + od, DD, DD, q2f + od, k2f + od, DD, DD,
               out, nullptr, LL, len, m0, n0);
}

// out = attn @ vp. attn cols >= len are exactly 0 -> mask K.
__global__ __launch_bounds__(NT, 1)
void tc_av(const float* __restrict__ attn, const float* __restrict__ vpt,
           const int* __restrict__ lens, float* __restrict__ ov)
{
    const int b = blockIdx.z;
    const int m0 = blockIdx.y * 128, n0 = blockIdx.x * 128;
    const int kmax = ((lens[b] + SLAB - 1) / SLAB) * SLAB;
    tc_body<0>(attn + (size_t)b * LL * LL, vpt + (size_t)b * DD * LL, kmax, LL,
               nullptr, nullptr, 0, 0, ov + (size_t)b * LL * DD, nullptr, DD, 0, m0, n0);
}

__global__ __launch_bounds__(NT, 1)
void tc_fc(const float* __restrict__ ov, const float* __restrict__ w_fc,
           const float* __restrict__ q, float* __restrict__ out)
{
    const int m0 = blockIdx.y * 128, n0 = blockIdx.x * 128;
    tc_body<1>(ov, w_fc, DD, DD, nullptr, nullptr, 0, 0, out, q, DD, 0, m0, n0);
}

// ---------------------------------------------------------------------------
// fa kernel: 8 rows per block (1024 blocks), x[b] cached in smem, warp-per-row.
// fa[b,i,j] = softmax_j( mask(j) ? sum_f |x[b,i,f]-x[b,j,f]| * fi[f] : -inf )
// ---------------------------------------------------------------------------
__global__ __launch_bounds__(256)
void fa_kernel(const float* __restrict__ x, const float* __restrict__ fi,
               const int* __restrict__ lens, float* __restrict__ fa)
{
    __shared__ float xs[LL*FF];
    __shared__ float fis[FF];
    const int blk = blockIdx.x;
    const int b = blk >> 7, rb = blk & 127;   // 128 blocks per batch, 8 rows each
    const int tid = threadIdx.x;
    const float* xb = x + (size_t)b * LL * FF;
    for (int i = tid; i < LL*FF; i += 256) xs[i] = xb[i];
    if (tid < FF) fis[tid] = fi[tid];
    __syncthreads();
    const int len = lens[b];
    const int lane = tid & 31, warp = tid >> 5;

    const int i = rb*8 + warp;
    float xi[FF];
    #pragma unroll
    for (int f = 0; f < FF; f++) xi[f] = xs[i*FF + f];
    float vals[32];
    float m = -INFINITY;
    #pragma unroll
    for (int it = 0; it < 32; it++) {
        const int j = lane + it*32;
        float s = 0.f;
        #pragma unroll
        for (int f = 0; f < FF; f++) s += fabsf(xi[f] - xs[j*FF + f]) * fis[f];
        s = (j < len) ? s : -INFINITY;
        vals[it] = s;
        m = fmaxf(m, s);
    }
    #pragma unroll
    for (int o = 16; o; o >>= 1) m = fmaxf(m, __shfl_xor_sync(~0u, m, o));
    float sum = 0.f;
    #pragma unroll
    for (int it = 0; it < 32; it++) {
        float e = expf(vals[it] - m);
        vals[it] = e;
        sum += e;
    }
    #pragma unroll
    for (int o = 16; o; o >>= 1) sum += __shfl_xor_sync(~0u, sum, o);
    const float inv = 1.f / sum;
    float* outp = fa + ((size_t)b*LL + i) * LL;
    #pragma unroll
    for (int it = 0; it < 32; it++)
        outp[lane + it*32] = vals[it] * inv;
}

// ---------------------------------------------------------------------------
// LayerNorm
// ---------------------------------------------------------------------------
__global__ __launch_bounds__(256)
void ln_kernel(const float* __restrict__ in, const float* __restrict__ gamma,
               const float* __restrict__ beta, float* __restrict__ out)
{
    const int row = blockIdx.x;
    const int t = threadIdx.x;
    __shared__ float red[256];
    const float v = in[(size_t)row*DD + t];
    red[t] = v; __syncthreads();
    for (int s = 128; s > 0; s >>= 1) {
        if (t < s) red[t] += red[t+s];
        __syncthreads();
    }
    const float mean = red[0] * (1.0f/DD);
    __syncthreads();
    const float d = v - mean;
    red[t] = d * d; __syncthreads();
    for (int s = 128; s > 0; s >>= 1) {
        if (t < s) red[t] += red[t+s];
        __syncthreads();
    }
    const float var = red[0] * (1.0f/DD);
    out[(size_t)row*DD + t] = d * rsqrtf(var + LN_EPS) * gamma[t] + beta[t];
}

// ---------------------------------------------------------------------------
// Host launch (multi-stream fork for independent stages; streams/events
// created once on the uncaptured correctness call, reused under capture)
// ---------------------------------------------------------------------------
static cudaStream_t s_fa = nullptr, s_p2 = nullptr;
static cudaEvent_t  e_root = nullptr, e_fa = nullptr, e_p2 = nullptr;

extern "C" void kernel_launch(void* const* d_in, const int* in_sizes, int n_in,
                              void* d_out, int out_size)
{
    int li = -1;
    for (int i = 0; i < n_in; i++) if (in_sizes[i] == BB) { li = i; break; }

    const float* q = (const float*)d_in[0];
    const float* k = (const float*)d_in[1];
    const float* v = (const float*)d_in[2];
    const float* x = (const float*)d_in[3];
    const int* lens;
    const float *w_qs, *w_ks, *w_vs, *w_qs2, *w_ks2, *w_fc, *fi, *gamma, *beta;
    if (li == 4) {
        lens  = (const int*)d_in[4];
        w_qs  = (const float*)d_in[5];  w_ks  = (const float*)d_in[6];
        w_vs  = (const float*)d_in[7];  w_qs2 = (const float*)d_in[8];
        w_ks2 = (const float*)d_in[9];  w_fc  = (const float*)d_in[10];
        fi    = (const float*)d_in[11]; gamma = (const float*)d_in[12];
        beta  = (const float*)d_in[13];
    } else {
        w_qs  = (const float*)d_in[4];  w_ks  = (const float*)d_in[5];
        w_vs  = (const float*)d_in[6];  w_qs2 = (const float*)d_in[7];
        w_ks2 = (const float*)d_in[8];  w_fc  = (const float*)d_in[9];
        fi    = (const float*)d_in[10]; gamma = (const float*)d_in[11];
        beta  = (const float*)d_in[12]; lens  = (const int*)d_in[13];
    }

    float *qp, *kp, *q2t, *k2t, *vpt, *q2f, *k2f, *ov, *fc, *fa, *attn_scratch;
    cudaGetSymbolAddress((void**)&qp,  g_qp);
    cudaGetSymbolAddress((void**)&kp,  g_kp);
    cudaGetSymbolAddress((void**)&q2t, g_q2t);
    cudaGetSymbolAddress((void**)&k2t, g_k2t);
    cudaGetSymbolAddress((void**)&vpt, g_vpt);
    cudaGetSymbolAddress((void**)&q2f, g_q2f);
    cudaGetSymbolAddress((void**)&k2f, g_k2f);
    cudaGetSymbolAddress((void**)&ov,  g_ov);
    cudaGetSymbolAddress((void**)&fc,  g_fc);
    cudaGetSymbolAddress((void**)&fa,  g_fa);
    cudaGetSymbolAddress((void**)&attn_scratch, g_attn_scratch);

    const size_t OUT_ELEMS  = (size_t)BB*LL*DD;
    const size_t ATTN_ELEMS = (size_t)BB*LL*LL;
    float* attn = ((size_t)out_size >= OUT_ELEMS + ATTN_ELEMS)
                ? (float*)d_out + OUT_ELEMS
                : attn_scratch;

    if (!s_fa) {
        cudaStreamCreateWithFlags(&s_fa, cudaStreamNonBlocking);
        cudaStreamCreateWithFlags(&s_p2, cudaStreamNonBlocking);
        cudaEventCreateWithFlags(&e_root, cudaEventDisableTiming);
        cudaEventCreateWithFlags(&e_fa,   cudaEventDisableTiming);
        cudaEventCreateWithFlags(&e_p2,   cudaEventDisableTiming);
        cudaFuncSetAttribute(tc_proj_qk, cudaFuncAttributeMaxDynamicSharedMemorySize, SMEM_DYN);
        cudaFuncSetAttribute(tc_projT,   cudaFuncAttributeMaxDynamicSharedMemorySize, SMEM_DYN);
        cudaFuncSetAttribute(tc_dual,    cudaFuncAttributeMaxDynamicSharedMemorySize, SMEM_DYN);
        cudaFuncSetAttribute(tc_logits,  cudaFuncAttributeMaxDynamicSharedMemorySize, SMEM_DYN);
        cudaFuncSetAttribute(tc_av,      cudaFuncAttributeMaxDynamicSharedMemorySize, SMEM_DYN);
        cudaFuncSetAttribute(tc_fc,      cudaFuncAttributeMaxDynamicSharedMemorySize, SMEM_DYN);
    }

    const int M = BB * LL;  // 8192
    dim3 blk(NT);
    dim3 blk256(256);

    // Fork: fa and projT run concurrently with proj_qk.
    cudaEventRecord(e_root, 0);
    cudaStreamWaitEvent(s_fa, e_root, 0);
    cudaStreamWaitEvent(s_p2, e_root, 0);

    // feature-affinity softmax (stream s_fa)
    fa_kernel<<<BB*128, blk256, 0, s_fa>>>(x, fi, lens, fa);
    cudaEventRecord(e_fa, s_fa);

    // transposed projections q2t/k2t/vpt (stream s_p2)
    tc_projT<<<dim3(LL/128, DD/128, 3*BB), blk, SMEM_DYN, s_p2>>>(
        q, k, v, w_qs2, w_ks2, w_vs, q2t, k2t, vpt);
    cudaEventRecord(e_p2, s_p2);

    // qp, kp projections (default stream, concurrent with the above)
    tc_proj_qk<<<dim3(DD/128, M/128, 2), blk, SMEM_DYN>>>(q, k, w_qs, w_ks, qp, kp);

    // Join: dual needs fa + q2t/k2t
    cudaStreamWaitEvent(0, e_fa, 0);
    cudaStreamWaitEvent(0, e_p2, 0);

    // q2f = fa@q2, k2f = fa@k2 (K masked by len)
    tc_dual<<<dim3(DD/128, LL/128, BB*2), blk, SMEM_DYN>>>(fa, q2t, k2t, lens, q2f, k2f);

    // logits + mask + tanh (fully-masked n-tiles skipped)
    tc_logits<<<dim3(LL/128, LL/128, BB), blk, SMEM_DYN>>>(qp, kp, q2f, k2f, lens, attn);

    // out = attn @ vp (K masked by len)
    tc_av<<<dim3(DD/128, LL/128, BB), blk, SMEM_DYN>>>(attn, vpt, lens, ov);

    // fc + residual, then layernorm
    tc_fc<<<dim3(DD/128, M/128, 1), blk, SMEM_DYN>>>(ov, w_fc, q, fc);
    ln_kernel<<<M, blk256>>>(fc, gamma, beta, (float*)d_out);
}

// round 12
// speedup vs baseline: 2.3672x; 1.0624x over previous
#include <cuda_runtime.h>
#include <cuda_fp16.h>
#include <math.h>
#include <stdint.h>

// Problem constants
#define BB 8
#define LL 1024
#define DD 256
#define FF 11
#define TEMP_INV (1.0f/16.0f)
#define LN_EPS 1e-6f

// GEMM config: 128x128 CTA tile, K-slab 64, 16 warps (4m x 4n), warp tile 32x32
// fp16 2-pass: D = aH*bH + aH*bL  (dropped aL*b ~ 2^-11)
#define SLAB 64
#define TB 16384                // one 128x64 fp16 tile (128 rows x 128B)
#define BUFB (3*TB)             // AH BH BL = 48KB
#define SMEM_DYN (2*BUFB)       // 98304 (double buffered)
#define NT 512                  // threads per CTA

// ---------------------------------------------------------------------------
// Scratch
// ---------------------------------------------------------------------------
__device__ float g_qp [BB*LL*DD];
__device__ float g_kp [BB*LL*DD];
__device__ float g_q2t[BB*LL*DD];   // [b][d][t]
__device__ float g_k2t[BB*LL*DD];
__device__ float g_vpt[BB*LL*DD];
__device__ float g_q2f[BB*LL*DD];
__device__ float g_k2f[BB*LL*DD];
__device__ float g_ov [BB*LL*DD];
__device__ float g_fc [BB*LL*DD];
__device__ float g_fa [(size_t)BB*LL*LL];
__device__ float g_attn_scratch[(size_t)BB*LL*LL];

// ---------------------------------------------------------------------------
// Helpers
// ---------------------------------------------------------------------------
__device__ __forceinline__ uint32_t smem_u32(const void* p) {
    uint32_t a;
    asm("{ .reg .u64 t; cvta.to.shared.u64 t, %1; cvt.u32.u64 %0, t; }"
        : "=r"(a) : "l"(p));
    return a;
}

__device__ __forceinline__ void ldsm_x4(uint32_t* r, uint32_t a) {
    asm volatile("ldmatrix.sync.aligned.m8n8.x4.shared.b16 {%0,%1,%2,%3}, [%4];"
        : "=r"(r[0]), "=r"(r[1]), "=r"(r[2]), "=r"(r[3]) : "r"(a));
}

__device__ __forceinline__ void mma16816(float* c, const uint32_t* a, const uint32_t* b) {
    asm volatile("mma.sync.aligned.m16n8k16.row.col.f32.f16.f16.f32 "
        "{%0,%1,%2,%3}, {%4,%5,%6,%7}, {%8,%9}, {%0,%1,%2,%3};"
        : "+f"(c[0]), "+f"(c[1]), "+f"(c[2]), "+f"(c[3])
        : "r"(a[0]), "r"(a[1]), "r"(a[2]), "r"(a[3]), "r"(b[0]), "r"(b[1]));
}

__device__ __forceinline__ uint32_t pack_h2(float x, float y) {
    __half2 h = __floats2half2_rn(x, y);
    return *(uint32_t*)&h;
}

// Load a 128x64 fp32 tile into registers (4 float4 per thread, 512 threads).
__device__ __forceinline__
void ld_tile(const float* __restrict__ src, int r0, int ld, int k0,
             float4* v, int tid)
{
    #pragma unroll
    for (int i = 0; i < 4; i++) {
        int f = tid + (i << 9);
        int row = f >> 4, c4 = f & 15;
        v[i] = *(const float4*)(src + (size_t)(r0 + row) * ld + k0 + (c4 << 2));
    }
}

// A tile: fp16 hi only, SW128-swizzled.
__device__ __forceinline__
void st_tile_a(const float4* v, char* smem, uint32_t off, int tid)
{
    #pragma unroll
    for (int i = 0; i < 4; i++) {
        int f = tid + (i << 9);
        int row = f >> 4, c4 = f & 15;
        float4 a = v[i];
        uint32_t byte = (row << 7) + (c4 << 3);
        uint32_t sw = byte ^ ((byte >> 3) & 0x70);
        *(uint2*)(smem + off + sw) = make_uint2(pack_h2(a.x, a.y), pack_h2(a.z, a.w));
    }
}

// B tile: fp16 hi + lo (residual), SW128-swizzled.
__device__ __forceinline__
void st_tile_b(const float4* v, char* smem, uint32_t hiOff, uint32_t loOff, int tid)
{
    #pragma unroll
    for (int i = 0; i < 4; i++) {
        int f = tid + (i << 9);
        int row = f >> 4, c4 = f & 15;
        float4 a = v[i];
        __half2 h01 = __floats2half2_rn(a.x, a.y);
        __half2 h23 = __floats2half2_rn(a.z, a.w);
        float rx = a.x - __low2float(h01);
        float ry = a.y - __high2float(h01);
        float rz = a.z - __low2float(h23);
        float rw = a.w - __high2float(h23);
        uint32_t byte = (row << 7) + (c4 << 3);
        uint32_t sw = byte ^ ((byte >> 3) & 0x70);
        *(uint2*)(smem + hiOff + sw) = make_uint2(*(uint32_t*)&h01, *(uint32_t*)&h23);
        *(uint2*)(smem + loOff + sw) = make_uint2(pack_h2(rx, ry), pack_h2(rz, rw));
    }
}

// ---------------------------------------------------------------------------
// fp16x2 mma.sync GEMM body. NT: C[m,n] = sum_k A[m,k]*B[n,k] over
// (A1,B1,kext1,ld1) then (A2,B2,kext2,ld2). kext may be < ld (masked K).
// MODE: 0 plain, 1 +add residual, 2 tanh(acc/16) w/ col mask
// ---------------------------------------------------------------------------
template<int MODE>
__device__ __forceinline__
void tc_body(const float* __restrict__ A1, const float* __restrict__ B1,
             int k1, int ld1,
             const float* __restrict__ A2, const float* __restrict__ B2,
             int k2, int ld2,
             float* __restrict__ C, const float* __restrict__ add,
             int ldc, int len, int m0, int n0)
{
    extern __shared__ char smem[];
    const uint32_t sb = smem_u32(smem);
    const int tid = threadIdx.x;
    const int lane = tid & 31, wid = tid >> 5;
    const int wm = wid & 3, wn = wid >> 2;

    float acc[2][4][4] = {};

    // ldmatrix lane addressing (128B rows, SW128-style XOR)
    const int a_row = wm * 32 + (lane & 15);
    const uint32_t a_colp = (lane >> 4) << 4;
    const uint32_t a_xor = (uint32_t)(a_row & 7) << 4;
    const int b_row = wn * 32 + ((lane >> 4) << 3) + (lane & 7);
    const uint32_t b_colp = ((lane >> 3) & 1) << 4;
    const uint32_t b_xor = (uint32_t)(b_row & 7) << 4;

    const int n1 = k1 / SLAB;
    const int nslabs = n1 + (A2 ? k2 / SLAB : 0);

    float4 av[4], bv[4];
    // prologue: slab 0
    ld_tile(A1, m0, ld1, 0, av, tid);
    ld_tile(B1, n0, ld1, 0, bv, tid);
    st_tile_a(av, smem, 0, tid);
    st_tile_b(bv, smem, TB, 2*TB, tid);
    __syncthreads();

    for (int s = 0; s < nslabs; s++) {
        const uint32_t bo = (s & 1) * BUFB;
        const uint32_t bn = bo ^ BUFB;
        const bool has = (s + 1) < nslabs;
        const float *An = A1, *Bn = B1; int ldn = ld1, k0n = 0;
        if (has) {
            int sn = s + 1;
            if (sn < n1) { An = A1; Bn = B1; ldn = ld1; k0n = sn * SLAB; }
            else         { An = A2; Bn = B2; ldn = ld2; k0n = (sn - n1) * SLAB; }
        }

        #pragma unroll
        for (int kk = 0; kk < 4; kk++) {
            if (kk == 0 && has) ld_tile(An, m0, ldn, k0n, av, tid);
            if (kk == 2 && has) {
                st_tile_a(av, smem, bn, tid);
                ld_tile(Bn, n0, ldn, k0n, bv, tid);
            }
            if (kk == 3 && has) st_tile_b(bv, smem, bn + TB, bn + 2*TB, tid);

            const uint32_t kb = kk << 5;
            uint32_t bH[8], bL[8];
            {
                uint32_t r = (uint32_t)b_row << 7;
                uint32_t c = (kb + b_colp) ^ b_xor;
                ldsm_x4(bH + 0, sb + bo + TB + r + c);
                ldsm_x4(bH + 4, sb + bo + TB + r + 2048 + c);
                ldsm_x4(bL + 0, sb + bo + 2*TB + r + c);
                ldsm_x4(bL + 4, sb + bo + 2*TB + r + 2048 + c);
            }
            #pragma unroll
            for (int mt = 0; mt < 2; mt++) {
                uint32_t aH[4];
                uint32_t r = (uint32_t)(a_row + mt*16) << 7;
                uint32_t c = (kb + a_colp) ^ a_xor;
                ldsm_x4(aH, sb + bo + r + c);
                #pragma unroll
                for (int nt = 0; nt < 4; nt++) {
                    mma16816(acc[mt][nt], aH, bH + nt*2);
                    mma16816(acc[mt][nt], aH, bL + nt*2);
                }
            }
        }
        if (has) __syncthreads();
    }

    // epilogue
    const int mg = m0 + wm * 32;
    const int ng = n0 + wn * 32;
    const int rq = lane >> 2;
    const int cq = (lane & 3) << 1;
    #pragma unroll
    for (int mt = 0; mt < 2; mt++) {
        #pragma unroll
        for (int nt = 0; nt < 4; nt++) {
            const float* a4 = acc[mt][nt];
            const int r0 = mg + mt*16 + rq, r1 = r0 + 8;
            const int c0 = ng + nt*8 + cq;
            if (MODE == 0) {
                *(float2*)(C + (size_t)r0*ldc + c0) = make_float2(a4[0], a4[1]);
                *(float2*)(C + (size_t)r1*ldc + c0) = make_float2(a4[2], a4[3]);
            } else if (MODE == 1) {
                float2 x0 = *(const float2*)(add + (size_t)r0*ldc + c0);
                float2 x1 = *(const float2*)(add + (size_t)r1*ldc + c0);
                *(float2*)(C + (size_t)r0*ldc + c0) = make_float2(a4[0]+x0.x, a4[1]+x0.y);
                *(float2*)(C + (size_t)r1*ldc + c0) = make_float2(a4[2]+x1.x, a4[3]+x1.y);
            } else {
                float2 v0, v1;
                v0.x = (c0   < len) ? tanhf(a4[0]*TEMP_INV) : 0.f;
                v0.y = (c0+1 < len) ? tanhf(a4[1]*TEMP_INV) : 0.f;
                v1.x = (c0   < len) ? tanhf(a4[2]*TEMP_INV) : 0.f;
                v1.y = (c0+1 < len) ? tanhf(a4[3]*TEMP_INV) : 0.f;
                *(float2*)(C + (size_t)r0*ldc + c0) = v0;
                *(float2*)(C + (size_t)r1*ldc + c0) = v1;
            }
        }
    }
}

// ---------------------------------------------------------------------------
// Stage kernels
// ---------------------------------------------------------------------------
__global__ __launch_bounds__(NT, 1)
void tc_proj_qk(const float* __restrict__ q, const float* __restrict__ k,
                const float* __restrict__ w_qs, const float* __restrict__ w_ks,
                float* __restrict__ qp, float* __restrict__ kp)
{
    const int m0 = blockIdx.y * 128, n0 = blockIdx.x * 128;
    if (blockIdx.z == 0)
        tc_body<0>(q, w_qs, DD, DD, nullptr, nullptr, 0, 0, qp, nullptr, DD, 0, m0, n0);
    else
        tc_body<0>(k, w_ks, DD, DD, nullptr, nullptr, 0, 0, kp, nullptr, DD, 0, m0, n0);
}

// Transposed projections: C_b = W (256xK) . X_b^T -> [256,1024] = [d][t]
__global__ __launch_bounds__(NT, 1)
void tc_projT(const float* __restrict__ q, const float* __restrict__ k,
              const float* __restrict__ v,
              const float* __restrict__ w_qs2, const float* __restrict__ w_ks2,
              const float* __restrict__ w_vs,
              float* __restrict__ q2t, float* __restrict__ k2t,
              float* __restrict__ vpt)
{
    const int b = blockIdx.z / 3, w = blockIdx.z % 3;
    const int m0 = blockIdx.y * 128, n0 = blockIdx.x * 128;
    const float* W; const float* X; float* C;
    if      (w == 0) { W = w_qs2; X = q; C = q2t; }
    else if (w == 1) { W = w_ks2; X = k; C = k2t; }
    else             { W = w_vs;  X = v; C = vpt; }
    tc_body<0>(W, X + (size_t)b*LL*DD, DD, DD, nullptr, nullptr, 0, 0,
               C + (size_t)b*DD*LL, nullptr, LL, 0, m0, n0);
}

// q2f = fa @ q2 (as NT with q2t), k2f = fa @ k2. K masked to ceil(len/64)*64.
__global__ __launch_bounds__(NT, 1)
void tc_dual(const float* __restrict__ fa, const float* __restrict__ q2t,
             const float* __restrict__ k2t, const int* __restrict__ lens,
             float* __restrict__ q2f, float* __restrict__ k2f)
{
    const int b = blockIdx.z >> 1, sel = blockIdx.z & 1;
    const int m0 = blockIdx.y * 128, n0 = blockIdx.x * 128;
    const int kmax = ((lens[b] + SLAB - 1) / SLAB) * SLAB;   // fa cols >= len are 0
    const float* A = fa + (size_t)b * LL * LL;
    const float* B = (sel ? k2t : q2t) + (size_t)b * DD * LL;
    float* C = (sel ? k2f : q2f) + (size_t)b * LL * DD;
    tc_body<0>(A, B, kmax, LL, nullptr, nullptr, 0, 0, C, nullptr, DD, 0, m0, n0);
}

__global__ __launch_bounds__(NT, 1)
void tc_logits(const float* __restrict__ qp, const float* __restrict__ kp,
               const float* __restrict__ q2f, const float* __restrict__ k2f,
               const int* __restrict__ lens, float* __restrict__ attn)
{
    const int b = blockIdx.z;
    const size_t od = (size_t)b * LL * DD;
    const int m0 = blockIdx.y * 128, n0 = blockIdx.x * 128;
    const int len = lens[b];
    float* out = attn + (size_t)b * LL * LL;
    if (n0 >= len) {
        // whole n-tile masked: attn = 0, skip GEMM entirely
        const float4 z4 = make_float4(0.f, 0.f, 0.f, 0.f);
        for (int i = threadIdx.x; i < 128 * 32; i += NT) {
            int r = i >> 5, c4 = i & 31;
            *(float4*)(out + (size_t)(m0 + r) * LL + n0 + (c4 << 2)) = z4;
        }
        return;
    }
    tc_body<2>(qp + od, kp + od, DD, DD, q2f + od, k2f + od, DD, DD,
               out, nullptr, LL, len, m0, n0);
}

// out = attn @ vp. attn cols >= len are exactly 0 -> mask K.
__global__ __launch_bounds__(NT, 1)
void tc_av(const float* __restrict__ attn, const float* __restrict__ vpt,
           const int* __restrict__ lens, float* __restrict__ ov)
{
    const int b = blockIdx.z;
    const int m0 = blockIdx.y * 128, n0 = blockIdx.x * 128;
    const int kmax = ((lens[b] + SLAB - 1) / SLAB) * SLAB;
    tc_body<0>(attn + (size_t)b * LL * LL, vpt + (size_t)b * DD * LL, kmax, LL,
               nullptr, nullptr, 0, 0, ov + (size_t)b * LL * DD, nullptr, DD, 0, m0, n0);
}

__global__ __launch_bounds__(NT, 1)
void tc_fc(const float* __restrict__ ov, const float* __restrict__ w_fc,
           const float* __restrict__ q, float* __restrict__ out)
{
    const int m0 = blockIdx.y * 128, n0 = blockIdx.x * 128;
    tc_body<1>(ov, w_fc, DD, DD, nullptr, nullptr, 0, 0, out, q, DD, 0, m0, n0);
}

// ---------------------------------------------------------------------------
// fa kernel: 8 rows per block (1024 blocks), x[b] cached in smem, warp-per-row.
// fa[b,i,j] = softmax_j( mask(j) ? sum_f |x[b,i,f]-x[b,j,f]| * fi[f] : -inf )
// ---------------------------------------------------------------------------
__global__ __launch_bounds__(256)
void fa_kernel(const float* __restrict__ x, const float* __restrict__ fi,
               const int* __restrict__ lens, float* __restrict__ fa)
{
    __shared__ float xs[LL*FF];
    __shared__ float fis[FF];
    const int blk = blockIdx.x;
    const int b = blk >> 7, rb = blk & 127;   // 128 blocks per batch, 8 rows each
    const int tid = threadIdx.x;
    const float* xb = x + (size_t)b * LL * FF;
    for (int i = tid; i < LL*FF; i += 256) xs[i] = xb[i];
    if (tid < FF) fis[tid] = fi[tid];
    __syncthreads();
    const int len = lens[b];
    const int lane = tid & 31, warp = tid >> 5;

    const int i = rb*8 + warp;
    float xi[FF];
    #pragma unroll
    for (int f = 0; f < FF; f++) xi[f] = xs[i*FF + f];
    float vals[32];
    float m = -INFINITY;
    #pragma unroll
    for (int it = 0; it < 32; it++) {
        const int j = lane + it*32;
        float s = 0.f;
        #pragma unroll
        for (int f = 0; f < FF; f++) s += fabsf(xi[f] - xs[j*FF + f]) * fis[f];
        s = (j < len) ? s : -INFINITY;
        vals[it] = s;
        m = fmaxf(m, s);
    }
    #pragma unroll
    for (int o = 16; o; o >>= 1) m = fmaxf(m, __shfl_xor_sync(~0u, m, o));
    float sum = 0.f;
    #pragma unroll
    for (int it = 0; it < 32; it++) {
        float e = expf(vals[it] - m);
        vals[it] = e;
        sum += e;
    }
    #pragma unroll
    for (int o = 16; o; o >>= 1) sum += __shfl_xor_sync(~0u, sum, o);
    const float inv = 1.f / sum;
    float* outp = fa + ((size_t)b*LL + i) * LL;
    #pragma unroll
    for (int it = 0; it < 32; it++)
        outp[lane + it*32] = vals[it] * inv;
}

// ---------------------------------------------------------------------------
// LayerNorm: warp per row, 8 warps/block, shfl reductions only.
// grid = M/8 blocks.
// ---------------------------------------------------------------------------
__global__ __launch_bounds__(256)
void ln_kernel(const float* __restrict__ in, const float* __restrict__ gamma,
               const float* __restrict__ beta, float* __restrict__ out)
{
    __shared__ float gs[DD], bs[DD];
    const int tid = threadIdx.x;
    if (tid < DD) { gs[tid] = gamma[tid]; }
    else          { bs[tid - DD] = beta[tid - DD]; }
    // 256 threads cover gs; second half covers bs (DD == 256 needs both halves)
    if (tid < DD) { bs[tid] = beta[tid]; }
    __syncthreads();

    const int lane = tid & 31, warp = tid >> 5;
    const int row = blockIdx.x * 8 + warp;
    const float* rp = in + (size_t)row * DD + lane * 8;

    float4 a0 = *(const float4*)(rp);
    float4 a1 = *(const float4*)(rp + 4);
    float v[8] = {a0.x, a0.y, a0.z, a0.w, a1.x, a1.y, a1.z, a1.w};

    float sum = 0.f;
    #pragma unroll
    for (int i = 0; i < 8; i++) sum += v[i];
    #pragma unroll
    for (int o = 16; o; o >>= 1) sum += __shfl_xor_sync(~0u, sum, o);
    const float mean = sum * (1.0f/DD);

    float vs = 0.f;
    #pragma unroll
    for (int i = 0; i < 8; i++) { v[i] -= mean; vs += v[i] * v[i]; }
    #pragma unroll
    for (int o = 16; o; o >>= 1) vs += __shfl_xor_sync(~0u, vs, o);
    const float rstd = rsqrtf(vs * (1.0f/DD) + LN_EPS);

    float* op = out + (size_t)row * DD + lane * 8;
    const int c = lane * 8;
    float4 o0, o1;
    o0.x = v[0]*rstd*gs[c+0] + bs[c+0];
    o0.y = v[1]*rstd*gs[c+1] + bs[c+1];
    o0.z = v[2]*rstd*gs[c+2] + bs[c+2];
    o0.w = v[3]*rstd*gs[c+3] + bs[c+3];
    o1.x = v[4]*rstd*gs[c+4] + bs[c+4];
    o1.y = v[5]*rstd*gs[c+5] + bs[c+5];
    o1.z = v[6]*rstd*gs[c+6] + bs[c+6];
    o1.w = v[7]*rstd*gs[c+7] + bs[c+7];
    *(float4*)(op)     = o0;
    *(float4*)(op + 4) = o1;
}

// ---------------------------------------------------------------------------
// Host launch (multi-stream DAG; streams/events created once on the
// uncaptured correctness call, reused under capture)
// ---------------------------------------------------------------------------
static cudaStream_t s_fa = nullptr, s_p2 = nullptr, s_qk = nullptr;
static cudaEvent_t  e_root = nullptr, e_fa = nullptr, e_p2 = nullptr, e_qk = nullptr;

extern "C" void kernel_launch(void* const* d_in, const int* in_sizes, int n_in,
                              void* d_out, int out_size)
{
    int li = -1;
    for (int i = 0; i < n_in; i++) if (in_sizes[i] == BB) { li = i; break; }

    const float* q = (const float*)d_in[0];
    const float* k = (const float*)d_in[1];
    const float* v = (const float*)d_in[2];
    const float* x = (const float*)d_in[3];
    const int* lens;
    const float *w_qs, *w_ks, *w_vs, *w_qs2, *w_ks2, *w_fc, *fi, *gamma, *beta;
    if (li == 4) {
        lens  = (const int*)d_in[4];
        w_qs  = (const float*)d_in[5];  w_ks  = (const float*)d_in[6];
        w_vs  = (const float*)d_in[7];  w_qs2 = (const float*)d_in[8];
        w_ks2 = (const float*)d_in[9];  w_fc  = (const float*)d_in[10];
        fi    = (const float*)d_in[11]; gamma = (const float*)d_in[12];
        beta  = (const float*)d_in[13];
    } else {
        w_qs  = (const float*)d_in[4];  w_ks  = (const float*)d_in[5];
        w_vs  = (const float*)d_in[6];  w_qs2 = (const float*)d_in[7];
        w_ks2 = (const float*)d_in[8];  w_fc  = (const float*)d_in[9];
        fi    = (const float*)d_in[10]; gamma = (const float*)d_in[11];
        beta  = (const float*)d_in[12]; lens  = (const int*)d_in[13];
    }

    float *qp, *kp, *q2t, *k2t, *vpt, *q2f, *k2f, *ov, *fc, *fa, *attn_scratch;
    cudaGetSymbolAddress((void**)&qp,  g_qp);
    cudaGetSymbolAddress((void**)&kp,  g_kp);
    cudaGetSymbolAddress((void**)&q2t, g_q2t);
    cudaGetSymbolAddress((void**)&k2t, g_k2t);
    cudaGetSymbolAddress((void**)&vpt, g_vpt);
    cudaGetSymbolAddress((void**)&q2f, g_q2f);
    cudaGetSymbolAddress((void**)&k2f, g_k2f);
    cudaGetSymbolAddress((void**)&ov,  g_ov);
    cudaGetSymbolAddress((void**)&fc,  g_fc);
    cudaGetSymbolAddress((void**)&fa,  g_fa);
    cudaGetSymbolAddress((void**)&attn_scratch, g_attn_scratch);

    const size_t OUT_ELEMS  = (size_t)BB*LL*DD;
    const size_t ATTN_ELEMS = (size_t)BB*LL*LL;
    float* attn = ((size_t)out_size >= OUT_ELEMS + ATTN_ELEMS)
                ? (float*)d_out + OUT_ELEMS
                : attn_scratch;

    if (!s_fa) {
        cudaStreamCreateWithFlags(&s_fa, cudaStreamNonBlocking);
        cudaStreamCreateWithFlags(&s_p2, cudaStreamNonBlocking);
        cudaStreamCreateWithFlags(&s_qk, cudaStreamNonBlocking);
        cudaEventCreateWithFlags(&e_root, cudaEventDisableTiming);
        cudaEventCreateWithFlags(&e_fa,   cudaEventDisableTiming);
        cudaEventCreateWithFlags(&e_p2,   cudaEventDisableTiming);
        cudaEventCreateWithFlags(&e_qk,   cudaEventDisableTiming);
        cudaFuncSetAttribute(tc_proj_qk, cudaFuncAttributeMaxDynamicSharedMemorySize, SMEM_DYN);
        cudaFuncSetAttribute(tc_projT,   cudaFuncAttributeMaxDynamicSharedMemorySize, SMEM_DYN);
        cudaFuncSetAttribute(tc_dual,    cudaFuncAttributeMaxDynamicSharedMemorySize, SMEM_DYN);
        cudaFuncSetAttribute(tc_logits,  cudaFuncAttributeMaxDynamicSharedMemorySize, SMEM_DYN);
        cudaFuncSetAttribute(tc_av,      cudaFuncAttributeMaxDynamicSharedMemorySize, SMEM_DYN);
        cudaFuncSetAttribute(tc_fc,      cudaFuncAttributeMaxDynamicSharedMemorySize, SMEM_DYN);
    }

    const int M = BB * LL;  // 8192
    dim3 blk(NT);
    dim3 blk256(256);

    // Fork: fa, projT, proj_qk all independent.
    cudaEventRecord(e_root, 0);
    cudaStreamWaitEvent(s_fa, e_root, 0);
    cudaStreamWaitEvent(s_p2, e_root, 0);
    cudaStreamWaitEvent(s_qk, e_root, 0);

    // feature-affinity softmax (stream s_fa)
    fa_kernel<<<BB*128, blk256, 0, s_fa>>>(x, fi, lens, fa);
    cudaEventRecord(e_fa, s_fa);

    // transposed projections q2t/k2t/vpt (stream s_p2)
    tc_projT<<<dim3(LL/128, DD/128, 3*BB), blk, SMEM_DYN, s_p2>>>(
        q, k, v, w_qs2, w_ks2, w_vs, q2t, k2t, vpt);
    cudaEventRecord(e_p2, s_p2);

    // qp, kp projections (stream s_qk; only logits depends on this)
    tc_proj_qk<<<dim3(DD/128, M/128, 2), blk, SMEM_DYN, s_qk>>>(q, k, w_qs, w_ks, qp, kp);
    cudaEventRecord(e_qk, s_qk);

    // dual needs fa + q2t/k2t only — overlaps proj_qk's tail
    cudaStreamWaitEvent(0, e_fa, 0);
    cudaStreamWaitEvent(0, e_p2, 0);
    tc_dual<<<dim3(DD/128, LL/128, BB*2), blk, SMEM_DYN>>>(fa, q2t, k2t, lens, q2f, k2f);

    // logits needs qp/kp + q2f/k2f
    cudaStreamWaitEvent(0, e_qk, 0);
    tc_logits<<<dim3(LL/128, LL/128, BB), blk, SMEM_DYN>>>(qp, kp, q2f, k2f, lens, attn);

    // out = attn @ vp (K masked by len)
    tc_av<<<dim3(DD/128, LL/128, BB), blk, SMEM_DYN>>>(attn, vpt, lens, ov);

    // fc + residual, then layernorm (warp-per-row)
    tc_fc<<<dim3(DD/128, M/128, 1), blk, SMEM_DYN>>>(ov, w_fc, q, fc);
    ln_kernel<<<M/8, blk256>>>(fc, gamma, beta, (float*)d_out);
}